// round 2
// baseline (speedup 1.0000x reference)
#include <cuda_runtime.h>

#define Bb   64
#define Tt   320
#define Ee   1024
#define Hh   16
#define HS   64
#define NT   (Bb*Tt)      // 20480 tokens
#define FF   (4*Ee)       // 4096

// ---------------- scratch (device globals; no allocation allowed) ----------------
__device__ float g_h [NT*Ee];    // LN1 out, later reused for attention output
__device__ float g_q [NT*Ee];    // q, later reused for LN2 out
__device__ float g_k [NT*Ee];
__device__ float g_v [NT*Ee];
__device__ float g_x1[NT*Ee];    // x after attention residual
__device__ float g_u [NT*FF];    // FFN intermediate

// ---------------- LayerNorm: one block (256 thr) per token row ----------------
__global__ __launch_bounds__(256) void ln_kernel(
    const float* __restrict__ x, const float* __restrict__ w,
    const float* __restrict__ b, float* __restrict__ out)
{
    __shared__ float red0[8], red1[8];
    int tid = threadIdx.x;
    size_t row = blockIdx.x;
    const float4* xr = reinterpret_cast<const float4*>(x + row*Ee);
    float4 v4 = xr[tid];
    float s  = v4.x + v4.y + v4.z + v4.w;
    float s2 = v4.x*v4.x + v4.y*v4.y + v4.z*v4.z + v4.w*v4.w;
    #pragma unroll
    for (int off = 16; off; off >>= 1) {
        s  += __shfl_xor_sync(0xffffffffu, s,  off);
        s2 += __shfl_xor_sync(0xffffffffu, s2, off);
    }
    if ((tid & 31) == 0) { red0[tid>>5] = s; red1[tid>>5] = s2; }
    __syncthreads();
    if (tid == 0) {
        float a = 0.f, c = 0.f;
        #pragma unroll
        for (int i = 0; i < 8; i++) { a += red0[i]; c += red1[i]; }
        red0[0] = a; red1[0] = c;
    }
    __syncthreads();
    float mu  = red0[0] * (1.0f/Ee);
    float var = red1[0] * (1.0f/Ee) - mu*mu;
    float inv = rsqrtf(var + 1e-5f);
    float4 wv = reinterpret_cast<const float4*>(w)[tid];
    float4 bv = reinterpret_cast<const float4*>(b)[tid];
    float4 o;
    o.x = (v4.x - mu)*inv*wv.x + bv.x;
    o.y = (v4.y - mu)*inv*wv.y + bv.y;
    o.z = (v4.z - mu)*inv*wv.z + bv.z;
    o.w = (v4.w - mu)*inv*wv.w + bv.w;
    reinterpret_cast<float4*>(out + row*Ee)[tid] = o;
}

// ---------------- Generic tiled GEMM: C = epi(A[M,K] @ B[K,N]) ----------------
// BM=BN=64, BK=16, 256 threads, 4x4 microtile per thread.
template<bool RELU, bool RES>
__global__ __launch_bounds__(256) void gemm_kernel(
    const float* __restrict__ A, const float* __restrict__ Bm,
    const float* __restrict__ bias, const float* __restrict__ res,
    float* __restrict__ C, int K, int N)
{
    __shared__ float As[16*68];   // [k][m], padded stride 68
    __shared__ float Bs[16*64];   // [k][n]
    int tid = threadIdx.x;
    int tx = tid & 15, ty = tid >> 4;
    size_t row0 = (size_t)blockIdx.x * 64;
    int col0 = blockIdx.y * 64;

    int a_r = tid >> 2;            // 0..63
    int a_c = (tid & 3) * 4;       // 0,4,8,12
    int b_r = tid >> 4;            // 0..15
    int b_c = (tid & 15) * 4;      // 0..60

    const float* Ap = A + (row0 + a_r)*(size_t)K + a_c;
    const float* Bp = Bm + (size_t)b_r*N + col0 + b_c;

    float acc[4][4] = {};
    for (int k0 = 0; k0 < K; k0 += 16) {
        float4 av = *(const float4*)(Ap + k0);
        As[(a_c+0)*68 + a_r] = av.x;
        As[(a_c+1)*68 + a_r] = av.y;
        As[(a_c+2)*68 + a_r] = av.z;
        As[(a_c+3)*68 + a_r] = av.w;
        *(float4*)&Bs[b_r*64 + b_c] = *(const float4*)(Bp + (size_t)k0*N);
        __syncthreads();
        #pragma unroll
        for (int kk = 0; kk < 16; kk++) {
            float4 a = *(const float4*)&As[kk*68 + ty*4];
            float4 b = *(const float4*)&Bs[kk*64 + tx*4];
            acc[0][0] += a.x*b.x; acc[0][1] += a.x*b.y; acc[0][2] += a.x*b.z; acc[0][3] += a.x*b.w;
            acc[1][0] += a.y*b.x; acc[1][1] += a.y*b.y; acc[1][2] += a.y*b.z; acc[1][3] += a.y*b.w;
            acc[2][0] += a.z*b.x; acc[2][1] += a.z*b.y; acc[2][2] += a.z*b.z; acc[2][3] += a.z*b.w;
            acc[3][0] += a.w*b.x; acc[3][1] += a.w*b.y; acc[3][2] += a.w*b.z; acc[3][3] += a.w*b.w;
        }
        __syncthreads();
    }
    #pragma unroll
    for (int i = 0; i < 4; i++) {
        size_t r = row0 + ty*4 + i;
        #pragma unroll
        for (int j = 0; j < 4; j++) {
            int c = col0 + tx*4 + j;
            float v = acc[i][j] + bias[c];
            if (RELU) v = fmaxf(v, 0.0f);
            if (RES)  v += res[r*(size_t)N + c];
            C[r*(size_t)N + c] = v;
        }
    }
}

// ---------------- fused QKV projection per head ----------------
// grid (NT/64, 48): y -> (which = y/16 in {q,k,v}, head = y%16)
// W layout (H,E,HS): head slice is plain row-major [E,64].
__global__ __launch_bounds__(256) void qkv_kernel(
    const float* __restrict__ h,
    const float* __restrict__ Wq, const float* __restrict__ Wk, const float* __restrict__ Wv,
    float* __restrict__ q, float* __restrict__ k, float* __restrict__ v)
{
    __shared__ float As[16*68];
    __shared__ float Bs[16*64];
    int tid = threadIdx.x;
    int tx = tid & 15, ty = tid >> 4;
    int which = blockIdx.y >> 4;
    int head  = blockIdx.y & 15;
    const float* W = (which == 0 ? Wq : which == 1 ? Wk : Wv) + (size_t)head*Ee*HS;
    float* out = (which == 0 ? q : which == 1 ? k : v);

    size_t row0 = (size_t)blockIdx.x * 64;
    int a_r = tid >> 2;
    int a_c = (tid & 3) * 4;
    int b_r = tid >> 4;
    int b_c = (tid & 15) * 4;
    const float* Ap = h + (row0 + a_r)*(size_t)Ee + a_c;
    const float* Bp = W + (size_t)b_r*HS + b_c;

    float acc[4][4] = {};
    for (int k0 = 0; k0 < Ee; k0 += 16) {
        float4 av = *(const float4*)(Ap + k0);
        As[(a_c+0)*68 + a_r] = av.x;
        As[(a_c+1)*68 + a_r] = av.y;
        As[(a_c+2)*68 + a_r] = av.z;
        As[(a_c+3)*68 + a_r] = av.w;
        *(float4*)&Bs[b_r*64 + b_c] = *(const float4*)(Bp + (size_t)k0*HS);
        __syncthreads();
        #pragma unroll
        for (int kk = 0; kk < 16; kk++) {
            float4 a = *(const float4*)&As[kk*68 + ty*4];
            float4 b = *(const float4*)&Bs[kk*64 + tx*4];
            acc[0][0] += a.x*b.x; acc[0][1] += a.x*b.y; acc[0][2] += a.x*b.z; acc[0][3] += a.x*b.w;
            acc[1][0] += a.y*b.x; acc[1][1] += a.y*b.y; acc[1][2] += a.y*b.z; acc[1][3] += a.y*b.w;
            acc[2][0] += a.z*b.x; acc[2][1] += a.z*b.y; acc[2][2] += a.z*b.z; acc[2][3] += a.z*b.w;
            acc[3][0] += a.w*b.x; acc[3][1] += a.w*b.y; acc[3][2] += a.w*b.z; acc[3][3] += a.w*b.w;
        }
        __syncthreads();
    }
    #pragma unroll
    for (int i = 0; i < 4; i++) {
        int rowg = (int)row0 + ty*4 + i;
        int bb = rowg / Tt, t = rowg % Tt;
        float* orow = out + ((size_t)(bb*Hh + head)*Tt + t)*HS + tx*4;
        orow[0] = acc[i][0]; orow[1] = acc[i][1]; orow[2] = acc[i][2]; orow[3] = acc[i][3];
    }
}

// ---------------- flash-style causal attention ----------------
// grid (T/64 = 5, B*H = 1024), 256 threads, 64-row Q tile, 64-key KV tiles,
// online softmax. Writes out in [b,t,h*64+d] = row-major [NT, E] layout.
__global__ __launch_bounds__(256) void attn_kernel(
    const float* __restrict__ q, const float* __restrict__ k,
    const float* __restrict__ v, float* __restrict__ out)
{
    extern __shared__ float sm[];
    float* Qs = sm;              // 64*64
    float* Ks = Qs + 64*64;      // 64*65 (padded: read along d)
    float* Vs = Ks + 64*65;      // 64*64
    float* Ps = Vs + 64*64;      // 64*64

    int itile = blockIdx.x;
    int bh    = blockIdx.y;
    int tid = threadIdx.x;
    int tx = tid & 15, ty = tid >> 4;

    const float* Qg = q + ((size_t)bh*Tt + itile*64)*HS;
    const float* Kg = k + (size_t)bh*Tt*HS;
    const float* Vg = v + (size_t)bh*Tt*HS;

    // load + pre-scale Q by E^-0.5 (reference scales by full E, not head_size)
    const float sc = 0.03125f;   // 1/sqrt(1024)
    for (int s4 = tid; s4 < 64*16; s4 += 256) {
        int r = s4 >> 4, c = (s4 & 15) << 2;
        float4 t4 = *(const float4*)(Qg + r*64 + c);
        t4.x *= sc; t4.y *= sc; t4.z *= sc; t4.w *= sc;
        *(float4*)&Qs[r*64 + c] = t4;
    }

    float m_i[4] = {-1e30f, -1e30f, -1e30f, -1e30f};
    float l_i[4] = {0.f, 0.f, 0.f, 0.f};
    float o[4][4] = {};

    for (int jt = 0; jt <= itile; jt++) {
        const float* Kt = Kg + jt*64*64;
        const float* Vt = Vg + jt*64*64;
        for (int s4 = tid; s4 < 64*16; s4 += 256) {
            int r = s4 >> 4, c = (s4 & 15) << 2;
            float4 k4 = *(const float4*)(Kt + r*64 + c);
            Ks[r*65 + c+0] = k4.x; Ks[r*65 + c+1] = k4.y;
            Ks[r*65 + c+2] = k4.z; Ks[r*65 + c+3] = k4.w;
            *(float4*)&Vs[r*64 + c] = *(const float4*)(Vt + r*64 + c);
        }
        __syncthreads();

        // S = Q @ K^T (64x64 tile, 4x4 per thread)
        float s[4][4] = {};
        #pragma unroll 8
        for (int d = 0; d < 64; d++) {
            float a0 = Qs[(ty*4+0)*64 + d];
            float a1 = Qs[(ty*4+1)*64 + d];
            float a2 = Qs[(ty*4+2)*64 + d];
            float a3 = Qs[(ty*4+3)*64 + d];
            float b0 = Ks[(tx*4+0)*65 + d];
            float b1 = Ks[(tx*4+1)*65 + d];
            float b2 = Ks[(tx*4+2)*65 + d];
            float b3 = Ks[(tx*4+3)*65 + d];
            s[0][0]+=a0*b0; s[0][1]+=a0*b1; s[0][2]+=a0*b2; s[0][3]+=a0*b3;
            s[1][0]+=a1*b0; s[1][1]+=a1*b1; s[1][2]+=a1*b2; s[1][3]+=a1*b3;
            s[2][0]+=a2*b0; s[2][1]+=a2*b1; s[2][2]+=a2*b2; s[2][3]+=a2*b3;
            s[3][0]+=a3*b0; s[3][1]+=a3*b1; s[3][2]+=a3*b2; s[3][3]+=a3*b3;
        }

        if (jt == itile) {   // causal mask on the diagonal tile
            #pragma unroll
            for (int i = 0; i < 4; i++)
                #pragma unroll
                for (int j = 0; j < 4; j++)
                    if (tx*4 + j > ty*4 + i) s[i][j] = -1e30f;
        }

        // online softmax (row stats replicated across the 16 tx lanes)
        #pragma unroll
        for (int i = 0; i < 4; i++) {
            float mx = fmaxf(fmaxf(s[i][0], s[i][1]), fmaxf(s[i][2], s[i][3]));
            mx = fmaxf(mx, __shfl_xor_sync(0xffffffffu, mx, 1));
            mx = fmaxf(mx, __shfl_xor_sync(0xffffffffu, mx, 2));
            mx = fmaxf(mx, __shfl_xor_sync(0xffffffffu, mx, 4));
            mx = fmaxf(mx, __shfl_xor_sync(0xffffffffu, mx, 8));
            float mnew = fmaxf(m_i[i], mx);
            float corr = __expf(m_i[i] - mnew);
            float ps = 0.f;
            #pragma unroll
            for (int j = 0; j < 4; j++) {
                float p = __expf(s[i][j] - mnew);
                s[i][j] = p; ps += p;
            }
            ps += __shfl_xor_sync(0xffffffffu, ps, 1);
            ps += __shfl_xor_sync(0xffffffffu, ps, 2);
            ps += __shfl_xor_sync(0xffffffffu, ps, 4);
            ps += __shfl_xor_sync(0xffffffffu, ps, 8);
            l_i[i] = l_i[i]*corr + ps;
            m_i[i] = mnew;
            #pragma unroll
            for (int j = 0; j < 4; j++) o[i][j] *= corr;
            *(float4*)&Ps[(ty*4+i)*64 + tx*4] = make_float4(s[i][0], s[i][1], s[i][2], s[i][3]);
        }
        __syncthreads();

        // O += P @ V
        #pragma unroll 8
        for (int kk = 0; kk < 64; kk++) {
            float p0 = Ps[(ty*4+0)*64 + kk];
            float p1 = Ps[(ty*4+1)*64 + kk];
            float p2 = Ps[(ty*4+2)*64 + kk];
            float p3 = Ps[(ty*4+3)*64 + kk];
            float v0 = Vs[kk*64 + tx*4+0];
            float v1 = Vs[kk*64 + tx*4+1];
            float v2 = Vs[kk*64 + tx*4+2];
            float v3 = Vs[kk*64 + tx*4+3];
            o[0][0]+=p0*v0; o[0][1]+=p0*v1; o[0][2]+=p0*v2; o[0][3]+=p0*v3;
            o[1][0]+=p1*v0; o[1][1]+=p1*v1; o[1][2]+=p1*v2; o[1][3]+=p1*v3;
            o[2][0]+=p2*v0; o[2][1]+=p2*v1; o[2][2]+=p2*v2; o[2][3]+=p2*v3;
            o[3][0]+=p3*v0; o[3][1]+=p3*v1; o[3][2]+=p3*v2; o[3][3]+=p3*v3;
        }
        __syncthreads();
    }

    int b = bh >> 4, head = bh & 15;
    #pragma unroll
    for (int i = 0; i < 4; i++) {
        float invl = 1.0f / l_i[i];
        size_t rowtok = (size_t)b*Tt + itile*64 + ty*4 + i;
        float* orow = out + rowtok*Ee + head*HS + tx*4;
        orow[0] = o[i][0]*invl; orow[1] = o[i][1]*invl;
        orow[2] = o[i][2]*invl; orow[3] = o[i][3]*invl;
    }
}

// ---------------- launch ----------------
extern "C" void kernel_launch(void* const* d_in, const int* in_sizes, int n_in,
                              void* d_out, int out_size)
{
    const float* x    = (const float*)d_in[0];
    const float* Wq   = (const float*)d_in[1];
    const float* Wk   = (const float*)d_in[2];
    const float* Wv   = (const float*)d_in[3];
    const float* Wo   = (const float*)d_in[4];
    const float* bo   = (const float*)d_in[5];
    const float* W1   = (const float*)d_in[6];
    const float* b1   = (const float*)d_in[7];
    const float* W2   = (const float*)d_in[8];
    const float* b2   = (const float*)d_in[9];
    const float* ln1w = (const float*)d_in[10];
    const float* ln1b = (const float*)d_in[11];
    const float* ln2w = (const float*)d_in[12];
    const float* ln2b = (const float*)d_in[13];
    float* out = (float*)d_out;

    float *hP, *qP, *kP, *vP, *x1P, *uP;
    cudaGetSymbolAddress((void**)&hP,  g_h);
    cudaGetSymbolAddress((void**)&qP,  g_q);
    cudaGetSymbolAddress((void**)&kP,  g_k);
    cudaGetSymbolAddress((void**)&vP,  g_v);
    cudaGetSymbolAddress((void**)&x1P, g_x1);
    cudaGetSymbolAddress((void**)&uP,  g_u);

    const int ATTN_SMEM = (64*64 + 64*65 + 64*64 + 64*64) * 4;  // 65792 B
    cudaFuncSetAttribute(attn_kernel, cudaFuncAttributeMaxDynamicSharedMemorySize, ATTN_SMEM);

    // 1) h = LN1(x)
    ln_kernel<<<NT, 256>>>(x, ln1w, ln1b, hP);
    // 2) q,k,v projections (per-head GEMMs)
    qkv_kernel<<<dim3(NT/64, 48), 256>>>(hP, Wq, Wk, Wv, qP, kP, vP);
    // 3) attention -> reuse g_h as [NT, E] attention output
    attn_kernel<<<dim3(Tt/64, Bb*Hh), 256, ATTN_SMEM>>>(qP, kP, vP, hP);
    // 4) x1 = x + attn @ Wo + bo
    gemm_kernel<false, true><<<dim3(NT/64, Ee/64), 256>>>(hP, Wo, bo, x, x1P, Ee, Ee);
    // 5) h2 = LN2(x1) -> reuse g_q
    ln_kernel<<<NT, 256>>>(x1P, ln2w, ln2b, qP);
    // 6) u = relu(h2 @ W1 + b1)
    gemm_kernel<true, false><<<dim3(NT/64, FF/64), 256>>>(qP, W1, b1, nullptr, uP, Ee, FF);
    // 7) out = x1 + u @ W2 + b2
    gemm_kernel<false, true><<<dim3(NT/64, Ee/64), 256>>>(uP, W2, b2, x1P, out, FF, Ee);
}

// round 3
// speedup vs baseline: 2.9367x; 2.9367x over previous
#include <cuda_runtime.h>
#include <cstdint>

#define Bb   64
#define Tt   320
#define Ee   1024
#define Hh   16
#define HS   64
#define NT   (Bb*Tt)      // 20480 tokens
#define FF   (4*Ee)       // 4096

// ---------------- scratch (device globals; no allocation allowed) ----------------
__device__ float g_h [NT*Ee];      // LN1 out / attention output (rounded)
__device__ float g_q [NT*Ee];      // q, later LN2 out (rounded)
__device__ float g_k [NT*Ee];
__device__ float g_v [NT*Ee];
__device__ float g_x1[NT*Ee];      // x after attention residual (fp32)
__device__ float g_u [NT*FF];      // FFN intermediate (rounded)
__device__ float g_w [12*1024*1024]; // tf32-rounded weights: qkv(3M) wo(1M) w1(4M) w2(4M)

#define WOFF_Q  0
#define WOFF_K  (1024*1024)
#define WOFF_V  (2*1024*1024)
#define WOFF_O  (3*1024*1024)
#define WOFF_1  (4*1024*1024)
#define WOFF_2  (8*1024*1024)

__device__ __forceinline__ float tf32r(float x) {
    uint32_t u;
    asm("cvt.rna.tf32.f32 %0, %1;" : "=r"(u) : "f"(x));
    return __uint_as_float(u);
}

__device__ __forceinline__ void cpa16(uint32_t dst, const void* src) {
    asm volatile("cp.async.ca.shared.global [%0], [%1], 16;" :: "r"(dst), "l"(src));
}
__device__ __forceinline__ void cpa_commit() { asm volatile("cp.async.commit_group;"); }

// ---------------- weight rounding: dst = tf32_rna(src) ----------------
__global__ __launch_bounds__(256) void round_kernel(const float4* __restrict__ src,
                                                    float4* __restrict__ dst, int n4) {
    int i = blockIdx.x * 256 + threadIdx.x;
    if (i < n4) {
        float4 v = src[i];
        v.x = tf32r(v.x); v.y = tf32r(v.y); v.z = tf32r(v.z); v.w = tf32r(v.w);
        dst[i] = v;
    }
}

// ---------------- LayerNorm (rounded output -> feeds tf32 GEMM) ----------------
__global__ __launch_bounds__(256) void ln_kernel(
    const float* __restrict__ x, const float* __restrict__ w,
    const float* __restrict__ b, float* __restrict__ out)
{
    __shared__ float red0[8], red1[8];
    int tid = threadIdx.x;
    size_t row = blockIdx.x;
    const float4* xr = reinterpret_cast<const float4*>(x + row*Ee);
    float4 v4 = xr[tid];
    float s  = v4.x + v4.y + v4.z + v4.w;
    float s2 = v4.x*v4.x + v4.y*v4.y + v4.z*v4.z + v4.w*v4.w;
    #pragma unroll
    for (int off = 16; off; off >>= 1) {
        s  += __shfl_xor_sync(0xffffffffu, s,  off);
        s2 += __shfl_xor_sync(0xffffffffu, s2, off);
    }
    if ((tid & 31) == 0) { red0[tid>>5] = s; red1[tid>>5] = s2; }
    __syncthreads();
    if (tid == 0) {
        float a = 0.f, c = 0.f;
        #pragma unroll
        for (int i = 0; i < 8; i++) { a += red0[i]; c += red1[i]; }
        red0[0] = a; red1[0] = c;
    }
    __syncthreads();
    float mu  = red0[0] * (1.0f/Ee);
    float var = red1[0] * (1.0f/Ee) - mu*mu;
    float inv = rsqrtf(var + 1e-5f);
    float4 wv = reinterpret_cast<const float4*>(w)[tid];
    float4 bv = reinterpret_cast<const float4*>(b)[tid];
    float4 o;
    o.x = tf32r((v4.x - mu)*inv*wv.x + bv.x);
    o.y = tf32r((v4.y - mu)*inv*wv.y + bv.y);
    o.z = tf32r((v4.z - mu)*inv*wv.z + bv.z);
    o.w = tf32r((v4.w - mu)*inv*wv.w + bv.w);
    reinterpret_cast<float4*>(out + row*Ee)[tid] = o;
}

// ================= tf32 tensor-core GEMM =================
// C[M,N] = op(A[M,K] @ B[K,N] + bias) [+ res], 128x128x16 tiles, 256 thr,
// 8 warps (2x4), warp tile 64x32, mma.m16n8k8.tf32, 4-stage cp.async.
#define ASTRIDE       20                  // floats per A smem row (80B: bank-safe + 16B aligned)
#define A_FLOATS      (128*ASTRIDE)       // 2560
#define B_FLOATS      (16*128)            // 2048
#define STAGE_FLOATS  (A_FLOATS + B_FLOATS)
#define STAGES        4
#define GEMM_SMEM     (STAGES*STAGE_FLOATS*4)

__device__ __forceinline__ void mma_tf32(float* c, uint32_t a0, uint32_t a1,
                                         uint32_t a2, uint32_t a3,
                                         uint32_t b0, uint32_t b1) {
    asm volatile(
        "mma.sync.aligned.m16n8k8.row.col.f32.tf32.tf32.f32 "
        "{%0,%1,%2,%3}, {%4,%5,%6,%7}, {%8,%9}, {%0,%1,%2,%3};"
        : "+f"(c[0]), "+f"(c[1]), "+f"(c[2]), "+f"(c[3])
        : "r"(a0), "r"(a1), "r"(a2), "r"(a3), "r"(b0), "r"(b1));
}

__device__ __forceinline__ void ldsm4(uint32_t& a0, uint32_t& a1, uint32_t& a2,
                                      uint32_t& a3, uint32_t addr) {
    asm volatile("ldmatrix.sync.aligned.m8n8.x4.shared.b16 {%0,%1,%2,%3}, [%4];"
                 : "=r"(a0), "=r"(a1), "=r"(a2), "=r"(a3) : "r"(addr));
}

template<bool RELU, bool RES, bool ROUND>
__global__ __launch_bounds__(256, 2) void gemm_tf32(
    const float* __restrict__ A, const float* __restrict__ Bm,
    const float* __restrict__ bias, const float* __restrict__ res,
    float* __restrict__ C, int K, int N)
{
    extern __shared__ float sm[];
    uint32_t smb = (uint32_t)__cvta_generic_to_shared(sm);
    int tid = threadIdx.x, lane = tid & 31, warp = tid >> 5;
    int wm = warp >> 2, wn = warp & 3;
    size_t row0 = (size_t)blockIdx.x * 128;
    int col0 = blockIdx.y * 128;

    // cp.async source/dest (2 x 16B for A, 2 x 16B for B per thread per stage)
    const float* aS0 = A + (row0 + (tid >> 2)) * (size_t)K + (tid & 3) * 4;
    const float* aS1 = aS0 + (size_t)64 * K;
    const float* bS0 = Bm + (size_t)(tid >> 5) * N + col0 + (tid & 31) * 4;
    const float* bS1 = bS0 + (size_t)8 * N;
    uint32_t dA0 = smb + ((tid >> 2) * ASTRIDE + (tid & 3) * 4) * 4;
    uint32_t dA1 = dA0 + 64 * ASTRIDE * 4;
    uint32_t dB0 = smb + (A_FLOATS + (tid >> 5) * 128 + (tid & 31) * 4) * 4;
    uint32_t dB1 = dB0 + 8 * 128 * 4;
    const uint32_t stB = STAGE_FLOATS * 4;

    float acc[4][4][4];
    #pragma unroll
    for (int i = 0; i < 4; i++)
        #pragma unroll
        for (int j = 0; j < 4; j++)
            #pragma unroll
            for (int r = 0; r < 4; r++) acc[i][j][r] = 0.f;

    const int KT = K / 16;
    #pragma unroll
    for (int s = 0; s < STAGES - 1; s++) {
        uint32_t so = s * stB;
        cpa16(dA0 + so, aS0 + s * 16);
        cpa16(dA1 + so, aS1 + s * 16);
        cpa16(dB0 + so, bS0 + (size_t)s * 16 * N);
        cpa16(dB1 + so, bS1 + (size_t)s * 16 * N);
        cpa_commit();
    }

    uint32_t aLd = smb + ((wm*64 + (lane & 7) + ((lane >> 3) & 1) * 8) * ASTRIDE) * 4
                       + ((lane >> 4) & 1) * 16;
    const int bOff = A_FLOATS + (lane & 3) * 128 + wn * 32 + (lane >> 2);

    for (int kt = 0; kt < KT; ++kt) {
        asm volatile("cp.async.wait_group %0;" :: "n"(STAGES - 2));
        __syncthreads();
        int cur = kt % STAGES;
        int nk = kt + STAGES - 1;
        if (nk < KT) {
            uint32_t so = (nk % STAGES) * stB;
            cpa16(dA0 + so, aS0 + nk * 16);
            cpa16(dA1 + so, aS1 + nk * 16);
            cpa16(dB0 + so, bS0 + (size_t)nk * 16 * N);
            cpa16(dB1 + so, bS1 + (size_t)nk * 16 * N);
        }
        cpa_commit();

        uint32_t aBase = aLd + cur * stB;
        const uint32_t* bBase = (const uint32_t*)sm + cur * STAGE_FLOATS + bOff;
        #pragma unroll
        for (int ks = 0; ks < 2; ks++) {
            uint32_t b0[4], b1[4];
            #pragma unroll
            for (int nj = 0; nj < 4; nj++) {
                b0[nj] = bBase[ks*8*128 + nj*8];
                b1[nj] = bBase[ks*8*128 + 512 + nj*8];
            }
            #pragma unroll
            for (int mi = 0; mi < 4; mi++) {
                uint32_t a0, a1, a2, a3;
                ldsm4(a0, a1, a2, a3, aBase + mi * 16 * ASTRIDE * 4 + ks * 32);
                #pragma unroll
                for (int nj = 0; nj < 4; nj++)
                    mma_tf32(acc[mi][nj], a0, a1, a2, a3, b0[nj], b1[nj]);
            }
        }
    }

    #pragma unroll
    for (int mi = 0; mi < 4; mi++) {
        size_t r = row0 + wm*64 + mi*16 + (lane >> 2);
        #pragma unroll
        for (int nj = 0; nj < 4; nj++) {
            int c = col0 + wn*32 + nj*8 + 2*(lane & 3);
            float2 bb = *(const float2*)&bias[c];
            float v0 = acc[mi][nj][0] + bb.x, v1 = acc[mi][nj][1] + bb.y;
            float v2 = acc[mi][nj][2] + bb.x, v3 = acc[mi][nj][3] + bb.y;
            if (RELU) { v0 = fmaxf(v0,0.f); v1 = fmaxf(v1,0.f); v2 = fmaxf(v2,0.f); v3 = fmaxf(v3,0.f); }
            if (RES) {
                float2 r0 = *(const float2*)&res[r*(size_t)N + c];
                float2 r1 = *(const float2*)&res[(r+8)*(size_t)N + c];
                v0 += r0.x; v1 += r0.y; v2 += r1.x; v3 += r1.y;
            }
            if (ROUND) { v0 = tf32r(v0); v1 = tf32r(v1); v2 = tf32r(v2); v3 = tf32r(v3); }
            float2 o0 = {v0, v1}, o1 = {v2, v3};
            *(float2*)&C[r*(size_t)N + c] = o0;
            *(float2*)&C[(r+8)*(size_t)N + c] = o1;
        }
    }
}

// ---------------- QKV projection GEMM (B gathered per head, scattered output) ----------------
// N = 3072 logical cols: (which, head, d). K = 1024.
__global__ __launch_bounds__(256, 2) void qkv_tf32(
    const float* __restrict__ A, const float* __restrict__ Wr,
    float* __restrict__ q, float* __restrict__ k, float* __restrict__ v)
{
    extern __shared__ float sm[];
    uint32_t smb = (uint32_t)__cvta_generic_to_shared(sm);
    int tid = threadIdx.x, lane = tid & 31, warp = tid >> 5;
    int wm = warp >> 2, wn = warp & 3;
    size_t row0 = (size_t)blockIdx.x * 128;
    int col0 = blockIdx.y * 128;
    const int K = Ee;

    const float* aS0 = A + (row0 + (tid >> 2)) * (size_t)K + (tid & 3) * 4;
    const float* aS1 = aS0 + (size_t)64 * K;
    // this thread's B column: fixed across k
    int colT = col0 + (tid & 31) * 4;
    const float* W = Wr + (colT >> 10) * (1024*1024)      // which block
                        + (((colT >> 6) & 15) * Ee * HS)  // head slice
                        + (colT & 63);                    // d
    const float* bS0 = W + (tid >> 5) * HS;
    const float* bS1 = bS0 + 8 * HS;

    uint32_t dA0 = smb + ((tid >> 2) * ASTRIDE + (tid & 3) * 4) * 4;
    uint32_t dA1 = dA0 + 64 * ASTRIDE * 4;
    uint32_t dB0 = smb + (A_FLOATS + (tid >> 5) * 128 + (tid & 31) * 4) * 4;
    uint32_t dB1 = dB0 + 8 * 128 * 4;
    const uint32_t stB = STAGE_FLOATS * 4;

    float acc[4][4][4];
    #pragma unroll
    for (int i = 0; i < 4; i++)
        #pragma unroll
        for (int j = 0; j < 4; j++)
            #pragma unroll
            for (int r = 0; r < 4; r++) acc[i][j][r] = 0.f;

    const int KT = K / 16;
    #pragma unroll
    for (int s = 0; s < STAGES - 1; s++) {
        uint32_t so = s * stB;
        cpa16(dA0 + so, aS0 + s * 16);
        cpa16(dA1 + so, aS1 + s * 16);
        cpa16(dB0 + so, bS0 + s * 16 * HS);
        cpa16(dB1 + so, bS1 + s * 16 * HS);
        cpa_commit();
    }

    uint32_t aLd = smb + ((wm*64 + (lane & 7) + ((lane >> 3) & 1) * 8) * ASTRIDE) * 4
                       + ((lane >> 4) & 1) * 16;
    const int bOff = A_FLOATS + (lane & 3) * 128 + wn * 32 + (lane >> 2);

    for (int kt = 0; kt < KT; ++kt) {
        asm volatile("cp.async.wait_group %0;" :: "n"(STAGES - 2));
        __syncthreads();
        int cur = kt % STAGES;
        int nk = kt + STAGES - 1;
        if (nk < KT) {
            uint32_t so = (nk % STAGES) * stB;
            cpa16(dA0 + so, aS0 + nk * 16);
            cpa16(dA1 + so, aS1 + nk * 16);
            cpa16(dB0 + so, bS0 + nk * 16 * HS);
            cpa16(dB1 + so, bS1 + nk * 16 * HS);
        }
        cpa_commit();

        uint32_t aBase = aLd + cur * stB;
        const uint32_t* bBase = (const uint32_t*)sm + cur * STAGE_FLOATS + bOff;
        #pragma unroll
        for (int ks = 0; ks < 2; ks++) {
            uint32_t b0[4], b1[4];
            #pragma unroll
            for (int nj = 0; nj < 4; nj++) {
                b0[nj] = bBase[ks*8*128 + nj*8];
                b1[nj] = bBase[ks*8*128 + 512 + nj*8];
            }
            #pragma unroll
            for (int mi = 0; mi < 4; mi++) {
                uint32_t a0, a1, a2, a3;
                ldsm4(a0, a1, a2, a3, aBase + mi * 16 * ASTRIDE * 4 + ks * 32);
                #pragma unroll
                for (int nj = 0; nj < 4; nj++)
                    mma_tf32(acc[mi][nj], a0, a1, a2, a3, b0[nj], b1[nj]);
            }
        }
    }

    int which = col0 >> 10;
    float* outp = (which == 0) ? q : (which == 1) ? k : v;
    #pragma unroll
    for (int mi = 0; mi < 4; mi++) {
        int r = (int)row0 + wm*64 + mi*16 + (lane >> 2);
        #pragma unroll
        for (int nj = 0; nj < 4; nj++) {
            int c = col0 + wn*32 + nj*8 + 2*(lane & 3);
            int hd = (c >> 6) & 15, d = c & 63;
            int b0r = r / Tt, t0 = r - b0r*Tt;
            int b1r = (r+8) / Tt, t1 = (r+8) - b1r*Tt;
            float2 o0 = {acc[mi][nj][0], acc[mi][nj][1]};
            float2 o1 = {acc[mi][nj][2], acc[mi][nj][3]};
            *(float2*)&outp[((size_t)(b0r*Hh + hd)*Tt + t0)*HS + d] = o0;
            *(float2*)&outp[((size_t)(b1r*Hh + hd)*Tt + t1)*HS + d] = o1;
        }
    }
}

// ---------------- flash-style causal attention (fp32 SIMT, rounded output) ----------------
__global__ __launch_bounds__(256) void attn_kernel(
    const float* __restrict__ q, const float* __restrict__ k,
    const float* __restrict__ v, float* __restrict__ out)
{
    extern __shared__ float sm[];
    float* Qs = sm;              // 64*64
    float* Ks = Qs + 64*64;      // 64*65
    float* Vs = Ks + 64*65;      // 64*64
    float* Ps = Vs + 64*64;      // 64*64

    int itile = blockIdx.x;
    int bh    = blockIdx.y;
    int tid = threadIdx.x;
    int tx = tid & 15, ty = tid >> 4;

    const float* Qg = q + ((size_t)bh*Tt + itile*64)*HS;
    const float* Kg = k + (size_t)bh*Tt*HS;
    const float* Vg = v + (size_t)bh*Tt*HS;

    const float sc = 0.03125f;   // E^-0.5
    for (int s4 = tid; s4 < 64*16; s4 += 256) {
        int r = s4 >> 4, c = (s4 & 15) << 2;
        float4 t4 = *(const float4*)(Qg + r*64 + c);
        t4.x *= sc; t4.y *= sc; t4.z *= sc; t4.w *= sc;
        *(float4*)&Qs[r*64 + c] = t4;
    }

    float m_i[4] = {-1e30f, -1e30f, -1e30f, -1e30f};
    float l_i[4] = {0.f, 0.f, 0.f, 0.f};
    float o[4][4] = {};

    for (int jt = 0; jt <= itile; jt++) {
        const float* Kt = Kg + jt*64*64;
        const float* Vt = Vg + jt*64*64;
        for (int s4 = tid; s4 < 64*16; s4 += 256) {
            int r = s4 >> 4, c = (s4 & 15) << 2;
            float4 k4 = *(const float4*)(Kt + r*64 + c);
            Ks[r*65 + c+0] = k4.x; Ks[r*65 + c+1] = k4.y;
            Ks[r*65 + c+2] = k4.z; Ks[r*65 + c+3] = k4.w;
            *(float4*)&Vs[r*64 + c] = *(const float4*)(Vt + r*64 + c);
        }
        __syncthreads();

        float s[4][4] = {};
        #pragma unroll 8
        for (int d = 0; d < 64; d++) {
            float a0 = Qs[(ty*4+0)*64 + d];
            float a1 = Qs[(ty*4+1)*64 + d];
            float a2 = Qs[(ty*4+2)*64 + d];
            float a3 = Qs[(ty*4+3)*64 + d];
            float b0 = Ks[(tx*4+0)*65 + d];
            float b1 = Ks[(tx*4+1)*65 + d];
            float b2 = Ks[(tx*4+2)*65 + d];
            float b3 = Ks[(tx*4+3)*65 + d];
            s[0][0]+=a0*b0; s[0][1]+=a0*b1; s[0][2]+=a0*b2; s[0][3]+=a0*b3;
            s[1][0]+=a1*b0; s[1][1]+=a1*b1; s[1][2]+=a1*b2; s[1][3]+=a1*b3;
            s[2][0]+=a2*b0; s[2][1]+=a2*b1; s[2][2]+=a2*b2; s[2][3]+=a2*b3;
            s[3][0]+=a3*b0; s[3][1]+=a3*b1; s[3][2]+=a3*b2; s[3][3]+=a3*b3;
        }

        if (jt == itile) {
            #pragma unroll
            for (int i = 0; i < 4; i++)
                #pragma unroll
                for (int j = 0; j < 4; j++)
                    if (tx*4 + j > ty*4 + i) s[i][j] = -1e30f;
        }

        #pragma unroll
        for (int i = 0; i < 4; i++) {
            float mx = fmaxf(fmaxf(s[i][0], s[i][1]), fmaxf(s[i][2], s[i][3]));
            mx = fmaxf(mx, __shfl_xor_sync(0xffffffffu, mx, 1));
            mx = fmaxf(mx, __shfl_xor_sync(0xffffffffu, mx, 2));
            mx = fmaxf(mx, __shfl_xor_sync(0xffffffffu, mx, 4));
            mx = fmaxf(mx, __shfl_xor_sync(0xffffffffu, mx, 8));
            float mnew = fmaxf(m_i[i], mx);
            float corr = __expf(m_i[i] - mnew);
            float ps = 0.f;
            #pragma unroll
            for (int j = 0; j < 4; j++) {
                float p = __expf(s[i][j] - mnew);
                s[i][j] = p; ps += p;
            }
            ps += __shfl_xor_sync(0xffffffffu, ps, 1);
            ps += __shfl_xor_sync(0xffffffffu, ps, 2);
            ps += __shfl_xor_sync(0xffffffffu, ps, 4);
            ps += __shfl_xor_sync(0xffffffffu, ps, 8);
            l_i[i] = l_i[i]*corr + ps;
            m_i[i] = mnew;
            #pragma unroll
            for (int j = 0; j < 4; j++) o[i][j] *= corr;
            *(float4*)&Ps[(ty*4+i)*64 + tx*4] = make_float4(s[i][0], s[i][1], s[i][2], s[i][3]);
        }
        __syncthreads();

        #pragma unroll 8
        for (int kk = 0; kk < 64; kk++) {
            float p0 = Ps[(ty*4+0)*64 + kk];
            float p1 = Ps[(ty*4+1)*64 + kk];
            float p2 = Ps[(ty*4+2)*64 + kk];
            float p3 = Ps[(ty*4+3)*64 + kk];
            float v0 = Vs[kk*64 + tx*4+0];
            float v1 = Vs[kk*64 + tx*4+1];
            float v2 = Vs[kk*64 + tx*4+2];
            float v3 = Vs[kk*64 + tx*4+3];
            o[0][0]+=p0*v0; o[0][1]+=p0*v1; o[0][2]+=p0*v2; o[0][3]+=p0*v3;
            o[1][0]+=p1*v0; o[1][1]+=p1*v1; o[1][2]+=p1*v2; o[1][3]+=p1*v3;
            o[2][0]+=p2*v0; o[2][1]+=p2*v1; o[2][2]+=p2*v2; o[2][3]+=p2*v3;
            o[3][0]+=p3*v0; o[3][1]+=p3*v1; o[3][2]+=p3*v2; o[3][3]+=p3*v3;
        }
        __syncthreads();
    }

    int b = bh >> 4, head = bh & 15;
    #pragma unroll
    for (int i = 0; i < 4; i++) {
        float invl = 1.0f / l_i[i];
        size_t rowtok = (size_t)b*Tt + itile*64 + ty*4 + i;
        float* orow = out + rowtok*Ee + head*HS + tx*4;
        orow[0] = tf32r(o[i][0]*invl); orow[1] = tf32r(o[i][1]*invl);
        orow[2] = tf32r(o[i][2]*invl); orow[3] = tf32r(o[i][3]*invl);
    }
}

// ---------------- launch ----------------
extern "C" void kernel_launch(void* const* d_in, const int* in_sizes, int n_in,
                              void* d_out, int out_size)
{
    const float* x    = (const float*)d_in[0];
    const float* Wq   = (const float*)d_in[1];
    const float* Wk   = (const float*)d_in[2];
    const float* Wv   = (const float*)d_in[3];
    const float* Wo   = (const float*)d_in[4];
    const float* bo   = (const float*)d_in[5];
    const float* W1   = (const float*)d_in[6];
    const float* b1   = (const float*)d_in[7];
    const float* W2   = (const float*)d_in[8];
    const float* b2   = (const float*)d_in[9];
    const float* ln1w = (const float*)d_in[10];
    const float* ln1b = (const float*)d_in[11];
    const float* ln2w = (const float*)d_in[12];
    const float* ln2b = (const float*)d_in[13];
    float* out = (float*)d_out;

    float *hP, *qP, *kP, *vP, *x1P, *uP, *wP;
    cudaGetSymbolAddress((void**)&hP,  g_h);
    cudaGetSymbolAddress((void**)&qP,  g_q);
    cudaGetSymbolAddress((void**)&kP,  g_k);
    cudaGetSymbolAddress((void**)&vP,  g_v);
    cudaGetSymbolAddress((void**)&x1P, g_x1);
    cudaGetSymbolAddress((void**)&uP,  g_u);
    cudaGetSymbolAddress((void**)&wP,  g_w);

    const int ATTN_SMEM = (64*64 + 64*65 + 64*64 + 64*64) * 4;  // 65792 B
    cudaFuncSetAttribute(attn_kernel, cudaFuncAttributeMaxDynamicSharedMemorySize, ATTN_SMEM);
    cudaFuncSetAttribute(qkv_tf32, cudaFuncAttributeMaxDynamicSharedMemorySize, GEMM_SMEM);
    cudaFuncSetAttribute(gemm_tf32<false,true,false>, cudaFuncAttributeMaxDynamicSharedMemorySize, GEMM_SMEM);
    cudaFuncSetAttribute(gemm_tf32<true,false,true>,  cudaFuncAttributeMaxDynamicSharedMemorySize, GEMM_SMEM);

    // 0) round weights to tf32 (unbiased RNA)
    const int M1 = 1024*1024;
    round_kernel<<<M1/1024, 256>>>((const float4*)Wq, (float4*)(wP+WOFF_Q), M1/4);
    round_kernel<<<M1/1024, 256>>>((const float4*)Wk, (float4*)(wP+WOFF_K), M1/4);
    round_kernel<<<M1/1024, 256>>>((const float4*)Wv, (float4*)(wP+WOFF_V), M1/4);
    round_kernel<<<M1/1024, 256>>>((const float4*)Wo, (float4*)(wP+WOFF_O), M1/4);
    round_kernel<<<4*M1/1024, 256>>>((const float4*)W1, (float4*)(wP+WOFF_1), M1);
    round_kernel<<<4*M1/1024, 256>>>((const float4*)W2, (float4*)(wP+WOFF_2), M1);

    // 1) h = round(LN1(x))
    ln_kernel<<<NT, 256>>>(x, ln1w, ln1b, hP);
    // 2) q,k,v = h @ Wqkv   (tf32 mma)
    qkv_tf32<<<dim3(NT/128, 24), 256, GEMM_SMEM>>>(hP, wP, qP, kP, vP);
    // 3) attention -> g_h (rounded)
    attn_kernel<<<dim3(Tt/64, Bb*Hh), 256, ATTN_SMEM>>>(qP, kP, vP, hP);
    // 4) x1 = x + attn @ Wo + bo
    gemm_tf32<false,true,false><<<dim3(NT/128, Ee/128), 256, GEMM_SMEM>>>(
        hP, wP+WOFF_O, bo, x, x1P, Ee, Ee);
    // 5) h2 = round(LN2(x1))
    ln_kernel<<<NT, 256>>>(x1P, ln2w, ln2b, qP);
    // 6) u = round(relu(h2 @ W1 + b1))
    gemm_tf32<true,false,true><<<dim3(NT/128, FF/128), 256, GEMM_SMEM>>>(
        qP, wP+WOFF_1, b1, nullptr, uP, Ee, FF);
    // 7) out = x1 + u @ W2 + b2
    gemm_tf32<false,true,false><<<dim3(NT/128, Ee/128), 256, GEMM_SMEM>>>(
        uP, wP+WOFF_2, b2, x1P, out, FF, Ee);
}

// round 4
// speedup vs baseline: 5.2540x; 1.7891x over previous
#include <cuda_runtime.h>
#include <cuda_fp16.h>
#include <cstdint>

#define Bb   64
#define Tt   320
#define Ee   1024
#define Hh   16
#define HS   64
#define NT   (Bb*Tt)
#define FF   (4*Ee)

__device__ __half g_h [NT*Ee];
__device__ __half g_q [NT*Ee];
__device__ __half g_k [NT*Ee];
__device__ __half g_v [NT*Ee];
__device__ float  g_x1[NT*Ee];
__device__ __half g_u [NT*FF];
__device__ __half g_w [12*1024*1024];

#define WOFF_Q  0
#define WOFF_O  (3*1024*1024)
#define WOFF_1  (4*1024*1024)
#define WOFF_2  (8*1024*1024)

__device__ __forceinline__ uint32_t h2u(float lo, float hi) {
    __half2 h = __floats2half2_rn(lo, hi);
    return *reinterpret_cast<uint32_t*>(&h);
}
__device__ __forceinline__ void cpa16(uint32_t dst, const void* src) {
    asm volatile("cp.async.cg.shared.global [%0], [%1], 16;" :: "r"(dst), "l"(src));
}
__device__ __forceinline__ void cpa_commit() { asm volatile("cp.async.commit_group;"); }

__device__ __forceinline__ void mma_f16(float* c, uint32_t a0, uint32_t a1,
                                        uint32_t a2, uint32_t a3,
                                        uint32_t b0, uint32_t b1) {
    asm volatile(
        "mma.sync.aligned.m16n8k16.row.col.f32.f16.f16.f32 "
        "{%0,%1,%2,%3}, {%4,%5,%6,%7}, {%8,%9}, {%0,%1,%2,%3};"
        : "+f"(c[0]), "+f"(c[1]), "+f"(c[2]), "+f"(c[3])
        : "r"(a0), "r"(a1), "r"(a2), "r"(a3), "r"(b0), "r"(b1));
}
__device__ __forceinline__ void ldsm4(uint32_t& r0, uint32_t& r1, uint32_t& r2,
                                      uint32_t& r3, uint32_t addr) {
    asm volatile("ldmatrix.sync.aligned.m8n8.x4.shared.b16 {%0,%1,%2,%3}, [%4];"
                 : "=r"(r0), "=r"(r1), "=r"(r2), "=r"(r3) : "r"(addr));
}
__device__ __forceinline__ void ldsm4t(uint32_t& r0, uint32_t& r1, uint32_t& r2,
                                       uint32_t& r3, uint32_t addr) {
    asm volatile("ldmatrix.sync.aligned.m8n8.x4.trans.shared.b16 {%0,%1,%2,%3}, [%4];"
                 : "=r"(r0), "=r"(r1), "=r"(r2), "=r"(r3) : "r"(addr));
}

__global__ __launch_bounds__(256) void roundh(const float4* __restrict__ src,
                                              uint2* __restrict__ dst, int n4) {
    int i = blockIdx.x * 256 + threadIdx.x;
    if (i < n4) {
        float4 v = src[i];
        uint2 p; p.x = h2u(v.x, v.y); p.y = h2u(v.z, v.w);
        dst[i] = p;
    }
}

__global__ __launch_bounds__(256) void ln_h(
    const float* __restrict__ x, const float* __restrict__ w,
    const float* __restrict__ b, __half* __restrict__ out)
{
    __shared__ float red0[8], red1[8];
    int tid = threadIdx.x;
    size_t row = blockIdx.x;
    const float4* xr = reinterpret_cast<const float4*>(x + row*Ee);
    float4 v4 = xr[tid];
    float s  = v4.x + v4.y + v4.z + v4.w;
    float s2 = v4.x*v4.x + v4.y*v4.y + v4.z*v4.z + v4.w*v4.w;
    #pragma unroll
    for (int off = 16; off; off >>= 1) {
        s  += __shfl_xor_sync(0xffffffffu, s,  off);
        s2 += __shfl_xor_sync(0xffffffffu, s2, off);
    }
    if ((tid & 31) == 0) { red0[tid>>5] = s; red1[tid>>5] = s2; }
    __syncthreads();
    if (tid == 0) {
        float a = 0.f, c = 0.f;
        #pragma unroll
        for (int i = 0; i < 8; i++) { a += red0[i]; c += red1[i]; }
        red0[0] = a; red1[0] = c;
    }
    __syncthreads();
    float mu  = red0[0] * (1.0f/Ee);
    float var = red1[0] * (1.0f/Ee) - mu*mu;
    float inv = rsqrtf(var + 1e-5f);
    float4 wv = reinterpret_cast<const float4*>(w)[tid];
    float4 bv = reinterpret_cast<const float4*>(b)[tid];
    uint2 pk;
    pk.x = h2u((v4.x - mu)*inv*wv.x + bv.x, (v4.y - mu)*inv*wv.y + bv.y);
    pk.y = h2u((v4.z - mu)*inv*wv.z + bv.z, (v4.w - mu)*inv*wv.w + bv.w);
    reinterpret_cast<uint2*>(out + row*Ee)[tid] = pk;
}

#define ASTRIDE  40
#define BSTRIDE  136
#define ABYTES   (128*ASTRIDE*2)
#define STB      (ABYTES + 32*BSTRIDE*2)
#define STAGES   3
#define GEMM_SMEM (STAGES*STB)

template<bool RELU, bool RES, bool HALFOUT>
__global__ __launch_bounds__(256, 2) void gemm_f16(
    const __half* __restrict__ A, const __half* __restrict__ Bm,
    const float* __restrict__ bias, const float* __restrict__ res,
    void* __restrict__ Cout, int K, int N)
{
    extern __shared__ __half smh[];
    uint32_t smb = (uint32_t)__cvta_generic_to_shared(smh);
    int tid = threadIdx.x, lane = tid & 31, warp = tid >> 5;
    int wm = warp >> 2, wn = warp & 3;
    size_t row0 = (size_t)blockIdx.x * 128;
    int col0 = blockIdx.y * 128;

    const __half* aS0 = A + (row0 + (tid >> 2)) * (size_t)K + (tid & 3) * 8;
    const __half* aS1 = aS0 + (size_t)64 * K;
    const __half* bS0 = Bm + (size_t)(tid >> 4) * N + col0 + (tid & 15) * 8;
    const __half* bS1 = bS0 + (size_t)16 * N;
    uint32_t dA0 = smb + ((tid >> 2) * ASTRIDE + (tid & 3) * 8) * 2;
    uint32_t dA1 = dA0 + 64 * ASTRIDE * 2;
    uint32_t dB0 = smb + ABYTES + ((tid >> 4) * BSTRIDE + (tid & 15) * 8) * 2;
    uint32_t dB1 = dB0 + 16 * BSTRIDE * 2;

    float acc[4][4][4];
    #pragma unroll
    for (int i = 0; i < 4; i++)
        #pragma unroll
        for (int j = 0; j < 4; j++)
            #pragma unroll
            for (int r = 0; r < 4; r++) acc[i][j][r] = 0.f;

    const int KT = K >> 5;
    #pragma unroll
    for (int s = 0; s < STAGES - 1; s++) {
        uint32_t so = s * STB;
        cpa16(dA0 + so, aS0 + s * 32);
        cpa16(dA1 + so, aS1 + s * 32);
        cpa16(dB0 + so, bS0 + (size_t)s * 32 * N);
        cpa16(dB1 + so, bS1 + (size_t)s * 32 * N);
        cpa_commit();
    }

    uint32_t aLd = smb + (wm*64 + (lane & 15)) * ASTRIDE * 2 + (lane >> 4) * 16;
    uint32_t bLd = smb + ABYTES + (lane & 15) * BSTRIDE * 2
                       + (wn*32 + (lane >> 4) * 8) * 2;

    for (int kt = 0; kt < KT; ++kt) {
        asm volatile("cp.async.wait_group %0;" :: "n"(STAGES - 2));
        __syncthreads();
        int cur = kt % STAGES;
        int nk = kt + STAGES - 1;
        if (nk < KT) {
            uint32_t so = (nk % STAGES) * STB;
            cpa16(dA0 + so, aS0 + nk * 32);
            cpa16(dA1 + so, aS1 + nk * 32);
            cpa16(dB0 + so, bS0 + (size_t)nk * 32 * N);
            cpa16(dB1 + so, bS1 + (size_t)nk * 32 * N);
        }
        cpa_commit();

        uint32_t aB = aLd + cur * STB;
        uint32_t bB = bLd + cur * STB;
        #pragma unroll
        for (int ks = 0; ks < 2; ks++) {
            uint32_t b[2][4];
            #pragma unroll
            for (int njj = 0; njj < 2; njj++)
                ldsm4t(b[njj][0], b[njj][1], b[njj][2], b[njj][3],
                       bB + ks * 16 * BSTRIDE * 2 + njj * 32);
            #pragma unroll
            for (int mi = 0; mi < 4; mi++) {
                uint32_t a0, a1, a2, a3;
                ldsm4(a0, a1, a2, a3, aB + mi * 16 * ASTRIDE * 2 + ks * 32);
                #pragma unroll
                for (int njj = 0; njj < 2; njj++) {
                    mma_f16(acc[mi][njj*2],   a0, a1, a2, a3, b[njj][0], b[njj][1]);
                    mma_f16(acc[mi][njj*2+1], a0, a1, a2, a3, b[njj][2], b[njj][3]);
                }
            }
        }
    }

    #pragma unroll
    for (int mi = 0; mi < 4; mi++) {
        size_t r = row0 + wm*64 + mi*16 + (lane >> 2);
        #pragma unroll
        for (int nj = 0; nj < 4; nj++) {
            int c = col0 + wn*32 + nj*8 + 2*(lane & 3);
            float2 bb = *(const float2*)&bias[c];
            float v0 = acc[mi][nj][0] + bb.x, v1 = acc[mi][nj][1] + bb.y;
            float v2 = acc[mi][nj][2] + bb.x, v3 = acc[mi][nj][3] + bb.y;
            if (RELU) { v0=fmaxf(v0,0.f); v1=fmaxf(v1,0.f); v2=fmaxf(v2,0.f); v3=fmaxf(v3,0.f); }
            if (RES) {
                float2 r0 = *(const float2*)&res[r*(size_t)N + c];
                float2 r1 = *(const float2*)&res[(r+8)*(size_t)N + c];
                v0 += r0.x; v1 += r0.y; v2 += r1.x; v3 += r1.y;
            }
            if (HALFOUT) {
                __half* Ch = (__half*)Cout;
                *(uint32_t*)&Ch[r*(size_t)N + c]     = h2u(v0, v1);
                *(uint32_t*)&Ch[(r+8)*(size_t)N + c] = h2u(v2, v3);
            } else {
                float* Cf = (float*)Cout;
                float2 o0 = {v0, v1}, o1 = {v2, v3};
                *(float2*)&Cf[r*(size_t)N + c]     = o0;
                *(float2*)&Cf[(r+8)*(size_t)N + c] = o1;
            }
        }
    }
}

__global__ __launch_bounds__(256, 2) void qkv_f16(
    const __half* __restrict__ A, const __half* __restrict__ Wh,
    __half* __restrict__ qo, __half* __restrict__ ko, __half* __restrict__ vo)
{
    extern __shared__ __half smh[];
    uint32_t smb = (uint32_t)__cvta_generic_to_shared(smh);
    int tid = threadIdx.x, lane = tid & 31, warp = tid >> 5;
    int wm = warp >> 2, wn = warp & 3;
    size_t row0 = (size_t)blockIdx.x * 128;
    int col0 = blockIdx.y * 128;
    const int K = Ee;

    const __half* aS0 = A + (row0 + (tid >> 2)) * (size_t)K + (tid & 3) * 8;
    const __half* aS1 = aS0 + (size_t)64 * K;
    int colT = col0 + (tid & 15) * 8;
    const __half* bS0 = Wh + ((size_t)(col0 >> 10) << 20)
                           + (size_t)((colT >> 6) & 15) * (Ee*HS)
                           + (size_t)(tid >> 4) * HS + (colT & 63);
    const __half* bS1 = bS0 + 16 * HS;

    uint32_t dA0 = smb + ((tid >> 2) * ASTRIDE + (tid & 3) * 8) * 2;
    uint32_t dA1 = dA0 + 64 * ASTRIDE * 2;
    uint32_t dB0 = smb + ABYTES + ((tid >> 4) * BSTRIDE + (tid & 15) * 8) * 2;
    uint32_t dB1 = dB0 + 16 * BSTRIDE * 2;

    float acc[4][4][4];
    #pragma unroll
    for (int i = 0; i < 4; i++)
        #pragma unroll
        for (int j = 0; j < 4; j++)
            #pragma unroll
            for (int r = 0; r < 4; r++) acc[i][j][r] = 0.f;

    const int KT = K >> 5;
    #pragma unroll
    for (int s = 0; s < STAGES - 1; s++) {
        uint32_t so = s * STB;
        cpa16(dA0 + so, aS0 + s * 32);
        cpa16(dA1 + so, aS1 + s * 32);
        cpa16(dB0 + so, bS0 + s * 32 * HS);
        cpa16(dB1 + so, bS1 + s * 32 * HS);
        cpa_commit();
    }

    uint32_t aLd = smb + (wm*64 + (lane & 15)) * ASTRIDE * 2 + (lane >> 4) * 16;
    uint32_t bLd = smb + ABYTES + (lane & 15) * BSTRIDE * 2
                       + (wn*32 + (lane >> 4) * 8) * 2;

    for (int kt = 0; kt < KT; ++kt) {
        asm volatile("cp.async.wait_group %0;" :: "n"(STAGES - 2));
        __syncthreads();
        int cur = kt % STAGES;
        int nk = kt + STAGES - 1;
        if (nk < KT) {
            uint32_t so = (nk % STAGES) * STB;
            cpa16(dA0 + so, aS0 + nk * 32);
            cpa16(dA1 + so, aS1 + nk * 32);
            cpa16(dB0 + so, bS0 + nk * 32 * HS);
            cpa16(dB1 + so, bS1 + nk * 32 * HS);
        }
        cpa_commit();

        uint32_t aB = aLd + cur * STB;
        uint32_t bB = bLd + cur * STB;
        #pragma unroll
        for (int ks = 0; ks < 2; ks++) {
            uint32_t b[2][4];
            #pragma unroll
            for (int njj = 0; njj < 2; njj++)
                ldsm4t(b[njj][0], b[njj][1], b[njj][2], b[njj][3],
                       bB + ks * 16 * BSTRIDE * 2 + njj * 32);
            #pragma unroll
            for (int mi = 0; mi < 4; mi++) {
                uint32_t a0, a1, a2, a3;
                ldsm4(a0, a1, a2, a3, aB + mi * 16 * ASTRIDE * 2 + ks * 32);
                #pragma unroll
                for (int njj = 0; njj < 2; njj++) {
                    mma_f16(acc[mi][njj*2],   a0, a1, a2, a3, b[njj][0], b[njj][1]);
                    mma_f16(acc[mi][njj*2+1], a0, a1, a2, a3, b[njj][2], b[njj][3]);
                }
            }
        }
    }

    int which = col0 >> 10;
    __half* outp = (which == 0) ? qo : (which == 1) ? ko : vo;
    float scl = (which == 0) ? 0.03125f : 1.0f;
    #pragma unroll
    for (int mi = 0; mi < 4; mi++) {
        int r = (int)row0 + wm*64 + mi*16 + (lane >> 2);
        int b0r = r / Tt, t0 = r - b0r*Tt;
        int b1r = (r+8) / Tt, t1 = (r+8) - b1r*Tt;
        #pragma unroll
        for (int nj = 0; nj < 4; nj++) {
            int c = col0 + wn*32 + nj*8 + 2*(lane & 3);
            int hd = (c >> 6) & 15, d = c & 63;
            *(uint32_t*)&outp[((size_t)(b0r*Hh + hd)*Tt + t0)*HS + d] =
                h2u(acc[mi][nj][0]*scl, acc[mi][nj][1]*scl);
            *(uint32_t*)&outp[((size_t)(b1r*Hh + hd)*Tt + t1)*HS + d] =
                h2u(acc[mi][nj][2]*scl, acc[mi][nj][3]*scl);
        }
    }
}

__global__ __launch_bounds__(128) void attn_f16(
    const __half* __restrict__ q, const __half* __restrict__ k,
    const __half* __restrict__ v, __half* __restrict__ out)
{
    __shared__ __half Qs[64*72], Ks[64*72], Vs[64*72];
    int itile = blockIdx.x, bh = blockIdx.y;
    int tid = threadIdx.x, lane = tid & 31, w = tid >> 5;
    uint32_t qb = (uint32_t)__cvta_generic_to_shared(Qs);
    uint32_t kb = (uint32_t)__cvta_generic_to_shared(Ks);
    uint32_t vb = (uint32_t)__cvta_generic_to_shared(Vs);

    const __half* Qg = q + ((size_t)bh*Tt + itile*64)*HS;
    const __half* Kg = k + (size_t)bh*Tt*HS;
    const __half* Vg = v + (size_t)bh*Tt*HS;

    for (int i = tid; i < 512; i += 128) {
        int r = i >> 3, c = (i & 7) * 8;
        *(uint4*)&Qs[r*72 + c] = *(const uint4*)&Qg[r*HS + c];
    }

    float m0 = -1e30f, m1 = -1e30f, l0 = 0.f, l1 = 0.f;
    float o[8][4];
    #pragma unroll
    for (int i = 0; i < 8; i++)
        #pragma unroll
        for (int j = 0; j < 4; j++) o[i][j] = 0.f;

    uint32_t qaddr = qb + (w*16 + (lane & 15)) * 144 + (lane >> 4) * 16;

    for (int jt = 0; jt <= itile; jt++) {
        __syncthreads();
        const __half* Kt = Kg + jt*64*HS;
        const __half* Vt = Vg + jt*64*HS;
        for (int i = tid; i < 512; i += 128) {
            int r = i >> 3, c = (i & 7) * 8;
            *(uint4*)&Ks[r*72 + c] = *(const uint4*)&Kt[r*HS + c];
            *(uint4*)&Vs[r*72 + c] = *(const uint4*)&Vt[r*HS + c];
        }
        __syncthreads();

        float s[8][4];
        #pragma unroll
        for (int i = 0; i < 8; i++)
            #pragma unroll
            for (int j = 0; j < 4; j++) s[i][j] = 0.f;

        #pragma unroll
        for (int ks = 0; ks < 4; ks++) {
            uint32_t a0, a1, a2, a3;
            ldsm4(a0, a1, a2, a3, qaddr + ks*32);
            #pragma unroll
            for (int njj = 0; njj < 4; njj++) {
                uint32_t b0, b1, b2, b3;
                ldsm4(b0, b1, b2, b3, kb + (njj*16 + (lane & 15))*144 + (lane >> 4)*16 + ks*32);
                mma_f16(s[njj*2],   a0, a1, a2, a3, b0, b2);
                mma_f16(s[njj*2+1], a0, a1, a2, a3, b1, b3);
            }
        }

        if (jt == itile) {
            int r0 = w*16 + (lane >> 2), r1 = r0 + 8;
            #pragma unroll
            for (int nj = 0; nj < 8; nj++) {
                int cb = nj*8 + 2*(lane & 3);
                if (cb   > r0) s[nj][0] = -1e30f;
                if (cb+1 > r0) s[nj][1] = -1e30f;
                if (cb   > r1) s[nj][2] = -1e30f;
                if (cb+1 > r1) s[nj][3] = -1e30f;
            }
        }

        float mx0 = -1e30f, mx1 = -1e30f;
        #pragma unroll
        for (int nj = 0; nj < 8; nj++) {
            mx0 = fmaxf(mx0, fmaxf(s[nj][0], s[nj][1]));
            mx1 = fmaxf(mx1, fmaxf(s[nj][2], s[nj][3]));
        }
        mx0 = fmaxf(mx0, __shfl_xor_sync(0xffffffffu, mx0, 1));
        mx0 = fmaxf(mx0, __shfl_xor_sync(0xffffffffu, mx0, 2));
        mx1 = fmaxf(mx1, __shfl_xor_sync(0xffffffffu, mx1, 1));
        mx1 = fmaxf(mx1, __shfl_xor_sync(0xffffffffu, mx1, 2));
        float mn0 = fmaxf(m0, mx0), mn1 = fmaxf(m1, mx1);
        float c0 = __expf(m0 - mn0), c1 = __expf(m1 - mn1);
        float ps0 = 0.f, ps1 = 0.f;
        #pragma unroll
        for (int nj = 0; nj < 8; nj++) {
            s[nj][0] = __expf(s[nj][0] - mn0); ps0 += s[nj][0];
            s[nj][1] = __expf(s[nj][1] - mn0); ps0 += s[nj][1];
            s[nj][2] = __expf(s[nj][2] - mn1); ps1 += s[nj][2];
            s[nj][3] = __expf(s[nj][3] - mn1); ps1 += s[nj][3];
        }
        ps0 += __shfl_xor_sync(0xffffffffu, ps0, 1);
        ps0 += __shfl_xor_sync(0xffffffffu, ps0, 2);
        ps1 += __shfl_xor_sync(0xffffffffu, ps1, 1);
        ps1 += __shfl_xor_sync(0xffffffffu, ps1, 2);
        l0 = l0*c0 + ps0; l1 = l1*c1 + ps1;
        m0 = mn0; m1 = mn1;
        #pragma unroll
        for (int nj = 0; nj < 8; nj++) {
            o[nj][0] *= c0; o[nj][1] *= c0; o[nj][2] *= c1; o[nj][3] *= c1;
        }

        #pragma unroll
        for (int ks = 0; ks < 4; ks++) {
            uint32_t pa0 = h2u(s[2*ks][0],   s[2*ks][1]);
            uint32_t pa1 = h2u(s[2*ks][2],   s[2*ks][3]);
            uint32_t pa2 = h2u(s[2*ks+1][0], s[2*ks+1][1]);
            uint32_t pa3 = h2u(s[2*ks+1][2], s[2*ks+1][3]);
            #pragma unroll
            for (int njj = 0; njj < 4; njj++) {
                uint32_t b0, b1, b2, b3;
                ldsm4t(b0, b1, b2, b3, vb + (ks*16 + (lane & 15))*144
                                           + (njj*16 + (lane >> 4)*8)*2);
                mma_f16(o[njj*2],   pa0, pa1, pa2, pa3, b0, b1);
                mma_f16(o[njj*2+1], pa0, pa1, pa2, pa3, b2, b3);
            }
        }
    }

    int b = bh >> 4, head = bh & 15;
    float inv0 = 1.0f / l0, inv1 = 1.0f / l1;
    int trow = itile*64 + w*16 + (lane >> 2);
    __half* o0p = out + ((size_t)b*Tt + trow)*Ee + head*HS;
    __half* o1p = o0p + (size_t)8*Ee;
    #pragma unroll
    for (int nj = 0; nj < 8; nj++) {
        int c = nj*8 + 2*(lane & 3);
        *(uint32_t*)&o0p[c] = h2u(o[nj][0]*inv0, o[nj][1]*inv0);
        *(uint32_t*)&o1p[c] = h2u(o[nj][2]*inv1, o[nj][3]*inv1);
    }
}

extern "C" void kernel_launch(void* const* d_in, const int* in_sizes, int n_in,
                              void* d_out, int out_size)
{
    const float* x    = (const float*)d_in[0];
    const float* Wq   = (const float*)d_in[1];
    const float* Wk   = (const float*)d_in[2];
    const float* Wv   = (const float*)d_in[3];
    const float* Wo   = (const float*)d_in[4];
    const float* bo   = (const float*)d_in[5];
    const float* W1   = (const float*)d_in[6];
    const float* b1   = (const float*)d_in[7];
    const float* W2   = (const float*)d_in[8];
    const float* b2   = (const float*)d_in[9];
    const float* ln1w = (const float*)d_in[10];
    const float* ln1b = (const float*)d_in[11];
    const float* ln2w = (const float*)d_in[12];
    const float* ln2b = (const float*)d_in[13];
    float* out = (float*)d_out;

    __half *hP, *qP, *kP, *vP, *uP, *wP;
    float *x1P;
    cudaGetSymbolAddress((void**)&hP,  g_h);
    cudaGetSymbolAddress((void**)&qP,  g_q);
    cudaGetSymbolAddress((void**)&kP,  g_k);
    cudaGetSymbolAddress((void**)&vP,  g_v);
    cudaGetSymbolAddress((void**)&x1P, g_x1);
    cudaGetSymbolAddress((void**)&uP,  g_u);
    cudaGetSymbolAddress((void**)&wP,  g_w);

    cudaFuncSetAttribute(qkv_f16, cudaFuncAttributeMaxDynamicSharedMemorySize, GEMM_SMEM);
    cudaFuncSetAttribute(gemm_f16<false,true,false>, cudaFuncAttributeMaxDynamicSharedMemorySize, GEMM_SMEM);
    cudaFuncSetAttribute(gemm_f16<true,false,true>,  cudaFuncAttributeMaxDynamicSharedMemorySize, GEMM_SMEM);

    const int M1 = 1024*1024;
    roundh<<<M1/1024, 256>>>((const float4*)Wq, (uint2*)(wP+WOFF_Q),      M1/4);
    roundh<<<M1/1024, 256>>>((const float4*)Wk, (uint2*)(wP+WOFF_Q+M1),   M1/4);
    roundh<<<M1/1024, 256>>>((const float4*)Wv, (uint2*)(wP+WOFF_Q+2*M1), M1/4);
    roundh<<<M1/1024, 256>>>((const float4*)Wo, (uint2*)(wP+WOFF_O),      M1/4);
    roundh<<<4*M1/1024, 256>>>((const float4*)W1, (uint2*)(wP+WOFF_1), M1);
    roundh<<<4*M1/1024, 256>>>((const float4*)W2, (uint2*)(wP+WOFF_2), M1);

    ln_h<<<NT, 256>>>(x, ln1w, ln1b, hP);
    qkv_f16<<<dim3(NT/128, 24), 256, GEMM_SMEM>>>(hP, wP, qP, kP, vP);
    attn_f16<<<dim3(Tt/64, Bb*Hh), 128>>>(qP, kP, vP, hP);
    gemm_f16<false,true,false><<<dim3(NT/128, Ee/128), 256, GEMM_SMEM>>>(
        hP, wP+WOFF_O, bo, x, x1P, Ee, Ee);
    ln_h<<<NT, 256>>>(x1P, ln2w, ln2b, qP);
    gemm_f16<true,false,true><<<dim3(NT/128, FF/128), 256, GEMM_SMEM>>>(
        qP, wP+WOFF_1, b1, nullptr, uP, Ee, FF);
    gemm_f16<false,true,false><<<dim3(NT/128, Ee/128), 256, GEMM_SMEM>>>(
        uP, wP+WOFF_2, b2, x1P, out, FF, Ee);
}

// round 6
// speedup vs baseline: 8.4840x; 1.6148x over previous
#include <cuda_runtime.h>
#include <cuda_fp16.h>
#include <cstdint>

#define Bb   64
#define Tt   320
#define Ee   1024
#define Hh   16
#define HS   64
#define NT   (Bb*Tt)
#define FF   (4*Ee)

__device__ __half g_h [NT*Ee];
__device__ __half g_q [NT*Ee];
__device__ __half g_k [NT*Ee];
__device__ __half g_v [NT*Ee];
__device__ float  g_x1[NT*Ee];
__device__ __half g_u [NT*FF];
__device__ __half g_w [12*1024*1024];

#define WOFF_Q  0
#define WOFF_O  (3*1024*1024)
#define WOFF_1  (4*1024*1024)
#define WOFF_2  (8*1024*1024)

__device__ __forceinline__ uint32_t h2u(float lo, float hi) {
    __half2 h = __floats2half2_rn(lo, hi);
    return *reinterpret_cast<uint32_t*>(&h);
}
__device__ __forceinline__ void cpa16(uint32_t dst, const void* src) {
    asm volatile("cp.async.cg.shared.global [%0], [%1], 16;" :: "r"(dst), "l"(src));
}
__device__ __forceinline__ void cpa_commit() { asm volatile("cp.async.commit_group;"); }

__device__ __forceinline__ void mma_f16(float* c, uint32_t a0, uint32_t a1,
                                        uint32_t a2, uint32_t a3,
                                        uint32_t b0, uint32_t b1) {
    asm volatile(
        "mma.sync.aligned.m16n8k16.row.col.f32.f16.f16.f32 "
        "{%0,%1,%2,%3}, {%4,%5,%6,%7}, {%8,%9}, {%0,%1,%2,%3};"
        : "+f"(c[0]), "+f"(c[1]), "+f"(c[2]), "+f"(c[3])
        : "r"(a0), "r"(a1), "r"(a2), "r"(a3), "r"(b0), "r"(b1));
}
__device__ __forceinline__ void ldsm4(uint32_t& r0, uint32_t& r1, uint32_t& r2,
                                      uint32_t& r3, uint32_t addr) {
    asm volatile("ldmatrix.sync.aligned.m8n8.x4.shared.b16 {%0,%1,%2,%3}, [%4];"
                 : "=r"(r0), "=r"(r1), "=r"(r2), "=r"(r3) : "r"(addr));
}
__device__ __forceinline__ void ldsm4t(uint32_t& r0, uint32_t& r1, uint32_t& r2,
                                       uint32_t& r3, uint32_t addr) {
    asm volatile("ldmatrix.sync.aligned.m8n8.x4.trans.shared.b16 {%0,%1,%2,%3}, [%4];"
                 : "=r"(r0), "=r"(r1), "=r"(r2), "=r"(r3) : "r"(addr));
}

// ---------------- prep: LN1 (blocks 0..NT-1) + weight fp32->fp16 convert ----------------
__global__ __launch_bounds__(256) void prep(
    const float* __restrict__ x, const float* __restrict__ ln1w,
    const float* __restrict__ ln1b, __half* __restrict__ hout,
    const float4* __restrict__ Wq, const float4* __restrict__ Wk,
    const float4* __restrict__ Wv, const float4* __restrict__ Wo,
    const float4* __restrict__ W1, const float4* __restrict__ W2,
    uint2* __restrict__ wdst)
{
    int blk = blockIdx.x;
    int tid = threadIdx.x;
    if (blk < NT) {
        __shared__ float red0[8], red1[8];
        size_t row = blk;
        const float4* xr = reinterpret_cast<const float4*>(x + row*Ee);
        float4 v4 = xr[tid];
        float s  = v4.x + v4.y + v4.z + v4.w;
        float s2 = v4.x*v4.x + v4.y*v4.y + v4.z*v4.z + v4.w*v4.w;
        #pragma unroll
        for (int off = 16; off; off >>= 1) {
            s  += __shfl_xor_sync(0xffffffffu, s,  off);
            s2 += __shfl_xor_sync(0xffffffffu, s2, off);
        }
        if ((tid & 31) == 0) { red0[tid>>5] = s; red1[tid>>5] = s2; }
        __syncthreads();
        if (tid == 0) {
            float a = 0.f, c = 0.f;
            #pragma unroll
            for (int i = 0; i < 8; i++) { a += red0[i]; c += red1[i]; }
            red0[0] = a; red1[0] = c;
        }
        __syncthreads();
        float mu  = red0[0] * (1.0f/Ee);
        float var = red1[0] * (1.0f/Ee) - mu*mu;
        float inv = rsqrtf(var + 1e-5f);
        float4 wv = reinterpret_cast<const float4*>(ln1w)[tid];
        float4 bv = reinterpret_cast<const float4*>(ln1b)[tid];
        uint2 pk;
        pk.x = h2u((v4.x - mu)*inv*wv.x + bv.x, (v4.y - mu)*inv*wv.y + bv.y);
        pk.y = h2u((v4.z - mu)*inv*wv.z + bv.z, (v4.w - mu)*inv*wv.w + bv.w);
        reinterpret_cast<uint2*>(hout + row*Ee)[tid] = pk;
    } else {
        int cb = blk - NT;           // 0..3071, each converts 1024 float4s
        #pragma unroll
        for (int it = 0; it < 4; it++) {
            int i = cb*1024 + it*256 + tid;   // f4 index in 0..3M
            const float4* src; int off;
            if      (i <  262144) { src = Wq; off = i; }
            else if (i <  524288) { src = Wk; off = i -  262144; }
            else if (i <  786432) { src = Wv; off = i -  524288; }
            else if (i < 1048576) { src = Wo; off = i -  786432; }
            else if (i < 2097152) { src = W1; off = i - 1048576; }
            else                  { src = W2; off = i - 2097152; }
            float4 v = src[off];
            uint2 p; p.x = h2u(v.x, v.y); p.y = h2u(v.z, v.w);
            wdst[i] = p;
        }
    }
}

// ---------------- LayerNorm fp32 -> half (used for LN2) ----------------
__global__ __launch_bounds__(256) void ln_h(
    const float* __restrict__ x, const float* __restrict__ w,
    const float* __restrict__ b, __half* __restrict__ out)
{
    __shared__ float red0[8], red1[8];
    int tid = threadIdx.x;
    size_t row = blockIdx.x;
    const float4* xr = reinterpret_cast<const float4*>(x + row*Ee);
    float4 v4 = xr[tid];
    float s  = v4.x + v4.y + v4.z + v4.w;
    float s2 = v4.x*v4.x + v4.y*v4.y + v4.z*v4.z + v4.w*v4.w;
    #pragma unroll
    for (int off = 16; off; off >>= 1) {
        s  += __shfl_xor_sync(0xffffffffu, s,  off);
        s2 += __shfl_xor_sync(0xffffffffu, s2, off);
    }
    if ((tid & 31) == 0) { red0[tid>>5] = s; red1[tid>>5] = s2; }
    __syncthreads();
    if (tid == 0) {
        float a = 0.f, c = 0.f;
        #pragma unroll
        for (int i = 0; i < 8; i++) { a += red0[i]; c += red1[i]; }
        red0[0] = a; red1[0] = c;
    }
    __syncthreads();
    float mu  = red0[0] * (1.0f/Ee);
    float var = red1[0] * (1.0f/Ee) - mu*mu;
    float inv = rsqrtf(var + 1e-5f);
    float4 wv = reinterpret_cast<const float4*>(w)[tid];
    float4 bv = reinterpret_cast<const float4*>(b)[tid];
    uint2 pk;
    pk.x = h2u((v4.x - mu)*inv*wv.x + bv.x, (v4.y - mu)*inv*wv.y + bv.y);
    pk.y = h2u((v4.z - mu)*inv*wv.z + bv.z, (v4.w - mu)*inv*wv.w + bv.w);
    reinterpret_cast<uint2*>(out + row*Ee)[tid] = pk;
}

#define ASTRIDE  40
#define BSTRIDE  136
#define ABYTES   (128*ASTRIDE*2)
#define STB      (ABYTES + 32*BSTRIDE*2)
#define STAGES   4
#define GEMM_SMEM (STAGES*STB)

template<bool RELU, bool RES, bool HALFOUT>
__global__ __launch_bounds__(256, 2) void gemm_f16(
    const __half* __restrict__ A, const __half* __restrict__ Bm,
    const float* __restrict__ bias, const float* __restrict__ res,
    void* __restrict__ Cout, int K, int N)
{
    extern __shared__ __half smh[];
    uint32_t smb = (uint32_t)__cvta_generic_to_shared(smh);
    int tid = threadIdx.x, lane = tid & 31, warp = tid >> 5;
    int wm = warp >> 2, wn = warp & 3;
    size_t row0 = (size_t)blockIdx.x * 128;
    int col0 = blockIdx.y * 128;

    const __half* aS0 = A + (row0 + (tid >> 2)) * (size_t)K + (tid & 3) * 8;
    const __half* aS1 = aS0 + (size_t)64 * K;
    const __half* bS0 = Bm + (size_t)(tid >> 4) * N + col0 + (tid & 15) * 8;
    const __half* bS1 = bS0 + (size_t)16 * N;
    uint32_t dA0 = smb + ((tid >> 2) * ASTRIDE + (tid & 3) * 8) * 2;
    uint32_t dA1 = dA0 + 64 * ASTRIDE * 2;
    uint32_t dB0 = smb + ABYTES + ((tid >> 4) * BSTRIDE + (tid & 15) * 8) * 2;
    uint32_t dB1 = dB0 + 16 * BSTRIDE * 2;

    float acc[4][4][4];
    #pragma unroll
    for (int i = 0; i < 4; i++)
        #pragma unroll
        for (int j = 0; j < 4; j++)
            #pragma unroll
            for (int r = 0; r < 4; r++) acc[i][j][r] = 0.f;

    const int KT = K >> 5;
    #pragma unroll
    for (int s = 0; s < STAGES - 1; s++) {
        uint32_t so = s * STB;
        cpa16(dA0 + so, aS0 + s * 32);
        cpa16(dA1 + so, aS1 + s * 32);
        cpa16(dB0 + so, bS0 + (size_t)s * 32 * N);
        cpa16(dB1 + so, bS1 + (size_t)s * 32 * N);
        cpa_commit();
    }

    uint32_t aLd = smb + (wm*64 + (lane & 15)) * ASTRIDE * 2 + (lane >> 4) * 16;
    uint32_t bLd = smb + ABYTES + (lane & 15) * BSTRIDE * 2
                       + (wn*32 + (lane >> 4) * 8) * 2;

    for (int kt = 0; kt < KT; ++kt) {
        asm volatile("cp.async.wait_group %0;" :: "n"(STAGES - 2));
        __syncthreads();
        int cur = kt % STAGES;
        int nk = kt + STAGES - 1;
        if (nk < KT) {
            uint32_t so = (nk % STAGES) * STB;
            cpa16(dA0 + so, aS0 + nk * 32);
            cpa16(dA1 + so, aS1 + nk * 32);
            cpa16(dB0 + so, bS0 + (size_t)nk * 32 * N);
            cpa16(dB1 + so, bS1 + (size_t)nk * 32 * N);
        }
        cpa_commit();

        uint32_t aB = aLd + cur * STB;
        uint32_t bB = bLd + cur * STB;
        #pragma unroll
        for (int ks = 0; ks < 2; ks++) {
            uint32_t b[2][4];
            #pragma unroll
            for (int njj = 0; njj < 2; njj++)
                ldsm4t(b[njj][0], b[njj][1], b[njj][2], b[njj][3],
                       bB + ks * 16 * BSTRIDE * 2 + njj * 32);
            #pragma unroll
            for (int mi = 0; mi < 4; mi++) {
                uint32_t a0, a1, a2, a3;
                ldsm4(a0, a1, a2, a3, aB + mi * 16 * ASTRIDE * 2 + ks * 32);
                #pragma unroll
                for (int njj = 0; njj < 2; njj++) {
                    mma_f16(acc[mi][njj*2],   a0, a1, a2, a3, b[njj][0], b[njj][1]);
                    mma_f16(acc[mi][njj*2+1], a0, a1, a2, a3, b[njj][2], b[njj][3]);
                }
            }
        }
    }

    #pragma unroll
    for (int mi = 0; mi < 4; mi++) {
        size_t r = row0 + wm*64 + mi*16 + (lane >> 2);
        #pragma unroll
        for (int nj = 0; nj < 4; nj++) {
            int c = col0 + wn*32 + nj*8 + 2*(lane & 3);
            float2 bb = *(const float2*)&bias[c];
            float v0 = acc[mi][nj][0] + bb.x, v1 = acc[mi][nj][1] + bb.y;
            float v2 = acc[mi][nj][2] + bb.x, v3 = acc[mi][nj][3] + bb.y;
            if (RELU) { v0=fmaxf(v0,0.f); v1=fmaxf(v1,0.f); v2=fmaxf(v2,0.f); v3=fmaxf(v3,0.f); }
            if (RES) {
                float2 r0 = *(const float2*)&res[r*(size_t)N + c];
                float2 r1 = *(const float2*)&res[(r+8)*(size_t)N + c];
                v0 += r0.x; v1 += r0.y; v2 += r1.x; v3 += r1.y;
            }
            if (HALFOUT) {
                __half* Ch = (__half*)Cout;
                *(uint32_t*)&Ch[r*(size_t)N + c]     = h2u(v0, v1);
                *(uint32_t*)&Ch[(r+8)*(size_t)N + c] = h2u(v2, v3);
            } else {
                float* Cf = (float*)Cout;
                float2 o0 = {v0, v1}, o1 = {v2, v3};
                *(float2*)&Cf[r*(size_t)N + c]     = o0;
                *(float2*)&Cf[(r+8)*(size_t)N + c] = o1;
            }
        }
    }
}

__global__ __launch_bounds__(256, 2) void qkv_f16(
    const __half* __restrict__ A, const __half* __restrict__ Wh,
    __half* __restrict__ qo, __half* __restrict__ ko, __half* __restrict__ vo)
{
    extern __shared__ __half smh[];
    uint32_t smb = (uint32_t)__cvta_generic_to_shared(smh);
    int tid = threadIdx.x, lane = tid & 31, warp = tid >> 5;
    int wm = warp >> 2, wn = warp & 3;
    size_t row0 = (size_t)blockIdx.x * 128;
    int col0 = blockIdx.y * 128;
    const int K = Ee;

    const __half* aS0 = A + (row0 + (tid >> 2)) * (size_t)K + (tid & 3) * 8;
    const __half* aS1 = aS0 + (size_t)64 * K;
    int colT = col0 + (tid & 15) * 8;
    const __half* bS0 = Wh + ((size_t)(col0 >> 10) << 20)
                           + (size_t)((colT >> 6) & 15) * (Ee*HS)
                           + (size_t)(tid >> 4) * HS + (colT & 63);
    const __half* bS1 = bS0 + 16 * HS;

    uint32_t dA0 = smb + ((tid >> 2) * ASTRIDE + (tid & 3) * 8) * 2;
    uint32_t dA1 = dA0 + 64 * ASTRIDE * 2;
    uint32_t dB0 = smb + ABYTES + ((tid >> 4) * BSTRIDE + (tid & 15) * 8) * 2;
    uint32_t dB1 = dB0 + 16 * BSTRIDE * 2;

    float acc[4][4][4];
    #pragma unroll
    for (int i = 0; i < 4; i++)
        #pragma unroll
        for (int j = 0; j < 4; j++)
            #pragma unroll
            for (int r = 0; r < 4; r++) acc[i][j][r] = 0.f;

    const int KT = K >> 5;
    #pragma unroll
    for (int s = 0; s < STAGES - 1; s++) {
        uint32_t so = s * STB;
        cpa16(dA0 + so, aS0 + s * 32);
        cpa16(dA1 + so, aS1 + s * 32);
        cpa16(dB0 + so, bS0 + s * 32 * HS);
        cpa16(dB1 + so, bS1 + s * 32 * HS);
        cpa_commit();
    }

    uint32_t aLd = smb + (wm*64 + (lane & 15)) * ASTRIDE * 2 + (lane >> 4) * 16;
    uint32_t bLd = smb + ABYTES + (lane & 15) * BSTRIDE * 2
                       + (wn*32 + (lane >> 4) * 8) * 2;

    for (int kt = 0; kt < KT; ++kt) {
        asm volatile("cp.async.wait_group %0;" :: "n"(STAGES - 2));
        __syncthreads();
        int cur = kt % STAGES;
        int nk = kt + STAGES - 1;
        if (nk < KT) {
            uint32_t so = (nk % STAGES) * STB;
            cpa16(dA0 + so, aS0 + nk * 32);
            cpa16(dA1 + so, aS1 + nk * 32);
            cpa16(dB0 + so, bS0 + nk * 32 * HS);
            cpa16(dB1 + so, bS1 + nk * 32 * HS);
        }
        cpa_commit();

        uint32_t aB = aLd + cur * STB;
        uint32_t bB = bLd + cur * STB;
        #pragma unroll
        for (int ks = 0; ks < 2; ks++) {
            uint32_t b[2][4];
            #pragma unroll
            for (int njj = 0; njj < 2; njj++)
                ldsm4t(b[njj][0], b[njj][1], b[njj][2], b[njj][3],
                       bB + ks * 16 * BSTRIDE * 2 + njj * 32);
            #pragma unroll
            for (int mi = 0; mi < 4; mi++) {
                uint32_t a0, a1, a2, a3;
                ldsm4(a0, a1, a2, a3, aB + mi * 16 * ASTRIDE * 2 + ks * 32);
                #pragma unroll
                for (int njj = 0; njj < 2; njj++) {
                    mma_f16(acc[mi][njj*2],   a0, a1, a2, a3, b[njj][0], b[njj][1]);
                    mma_f16(acc[mi][njj*2+1], a0, a1, a2, a3, b[njj][2], b[njj][3]);
                }
            }
        }
    }

    int which = col0 >> 10;
    __half* outp = (which == 0) ? qo : (which == 1) ? ko : vo;
    // q pre-scaled by E^-0.5 * log2(e) so attention runs softmax in exp2 domain
    float scl = (which == 0) ? 0.04508422f : 1.0f;
    #pragma unroll
    for (int mi = 0; mi < 4; mi++) {
        int r = (int)row0 + wm*64 + mi*16 + (lane >> 2);
        int b0r = r / Tt, t0 = r - b0r*Tt;
        int b1r = (r+8) / Tt, t1 = (r+8) - b1r*Tt;
        #pragma unroll
        for (int nj = 0; nj < 4; nj++) {
            int c = col0 + wn*32 + nj*8 + 2*(lane & 3);
            int hd = (c >> 6) & 15, d = c & 63;
            *(uint32_t*)&outp[((size_t)(b0r*Hh + hd)*Tt + t0)*HS + d] =
                h2u(acc[mi][nj][0]*scl, acc[mi][nj][1]*scl);
            *(uint32_t*)&outp[((size_t)(b1r*Hh + hd)*Tt + t1)*HS + d] =
                h2u(acc[mi][nj][2]*scl, acc[mi][nj][3]*scl);
        }
    }
}

__global__ __launch_bounds__(128) void attn_f16(
    const __half* __restrict__ q, const __half* __restrict__ k,
    const __half* __restrict__ v, __half* __restrict__ out)
{
    __shared__ __half Qs[64*72], Ks[64*72], Vs[64*72];
    int itile = blockIdx.x, bh = blockIdx.y;
    int tid = threadIdx.x, lane = tid & 31, w = tid >> 5;
    uint32_t qb = (uint32_t)__cvta_generic_to_shared(Qs);
    uint32_t kb = (uint32_t)__cvta_generic_to_shared(Ks);
    uint32_t vb = (uint32_t)__cvta_generic_to_shared(Vs);

    const __half* Qg = q + ((size_t)bh*Tt + itile*64)*HS;
    const __half* Kg = k + (size_t)bh*Tt*HS;
    const __half* Vg = v + (size_t)bh*Tt*HS;

    for (int i = tid; i < 512; i += 128) {
        int r = i >> 3, c = (i & 7) * 8;
        *(uint4*)&Qs[r*72 + c] = *(const uint4*)&Qg[r*HS + c];
    }

    float m0 = -1e30f, m1 = -1e30f, l0 = 0.f, l1 = 0.f;
    float o[8][4];
    #pragma unroll
    for (int i = 0; i < 8; i++)
        #pragma unroll
        for (int j = 0; j < 4; j++) o[i][j] = 0.f;

    uint32_t qaddr = qb + (w*16 + (lane & 15)) * 144 + (lane >> 4) * 16;

    for (int jt = 0; jt <= itile; jt++) {
        __syncthreads();
        const __half* Kt = Kg + jt*64*HS;
        const __half* Vt = Vg + jt*64*HS;
        for (int i = tid; i < 512; i += 128) {
            int r = i >> 3, c = (i & 7) * 8;
            *(uint4*)&Ks[r*72 + c] = *(const uint4*)&Kt[r*HS + c];
            *(uint4*)&Vs[r*72 + c] = *(const uint4*)&Vt[r*HS + c];
        }
        __syncthreads();

        float s[8][4];
        #pragma unroll
        for (int i = 0; i < 8; i++)
            #pragma unroll
            for (int j = 0; j < 4; j++) s[i][j] = 0.f;

        #pragma unroll
        for (int ks = 0; ks < 4; ks++) {
            uint32_t a0, a1, a2, a3;
            ldsm4(a0, a1, a2, a3, qaddr + ks*32);
            #pragma unroll
            for (int njj = 0; njj < 4; njj++) {
                uint32_t b0, b1, b2, b3;
                ldsm4(b0, b1, b2, b3, kb + (njj*16 + (lane & 15))*144 + (lane >> 4)*16 + ks*32);
                mma_f16(s[njj*2],   a0, a1, a2, a3, b0, b2);
                mma_f16(s[njj*2+1], a0, a1, a2, a3, b1, b3);
            }
        }

        if (jt == itile) {
            int r0 = w*16 + (lane >> 2), r1 = r0 + 8;
            #pragma unroll
            for (int nj = 0; nj < 8; nj++) {
                int cb = nj*8 + 2*(lane & 3);
                if (cb   > r0) s[nj][0] = -1e30f;
                if (cb+1 > r0) s[nj][1] = -1e30f;
                if (cb   > r1) s[nj][2] = -1e30f;
                if (cb+1 > r1) s[nj][3] = -1e30f;
            }
        }

        float mx0 = -1e30f, mx1 = -1e30f;
        #pragma unroll
        for (int nj = 0; nj < 8; nj++) {
            mx0 = fmaxf(mx0, fmaxf(s[nj][0], s[nj][1]));
            mx1 = fmaxf(mx1, fmaxf(s[nj][2], s[nj][3]));
        }
        mx0 = fmaxf(mx0, __shfl_xor_sync(0xffffffffu, mx0, 1));
        mx0 = fmaxf(mx0, __shfl_xor_sync(0xffffffffu, mx0, 2));
        mx1 = fmaxf(mx1, __shfl_xor_sync(0xffffffffu, mx1, 1));
        mx1 = fmaxf(mx1, __shfl_xor_sync(0xffffffffu, mx1, 2));
        float mn0 = fmaxf(m0, mx0), mn1 = fmaxf(m1, mx1);
        float c0 = exp2f(m0 - mn0), c1 = exp2f(m1 - mn1);
        float ps0 = 0.f, ps1 = 0.f;
        #pragma unroll
        for (int nj = 0; nj < 8; nj++) {
            s[nj][0] = exp2f(s[nj][0] - mn0); ps0 += s[nj][0];
            s[nj][1] = exp2f(s[nj][1] - mn0); ps0 += s[nj][1];
            s[nj][2] = exp2f(s[nj][2] - mn1); ps1 += s[nj][2];
            s[nj][3] = exp2f(s[nj][3] - mn1); ps1 += s[nj][3];
        }
        ps0 += __shfl_xor_sync(0xffffffffu, ps0, 1);
        ps0 += __shfl_xor_sync(0xffffffffu, ps0, 2);
        ps1 += __shfl_xor_sync(0xffffffffu, ps1, 1);
        ps1 += __shfl_xor_sync(0xffffffffu, ps1, 2);
        l0 = l0*c0 + ps0; l1 = l1*c1 + ps1;
        m0 = mn0; m1 = mn1;
        #pragma unroll
        for (int nj = 0; nj < 8; nj++) {
            o[nj][0] *= c0; o[nj][1] *= c0; o[nj][2] *= c1; o[nj][3] *= c1;
        }

        #pragma unroll
        for (int ks = 0; ks < 4; ks++) {
            uint32_t pa0 = h2u(s[2*ks][0],   s[2*ks][1]);
            uint32_t pa1 = h2u(s[2*ks][2],   s[2*ks][3]);
            uint32_t pa2 = h2u(s[2*ks+1][0], s[2*ks+1][1]);
            uint32_t pa3 = h2u(s[2*ks+1][2], s[2*ks+1][3]);
            #pragma unroll
            for (int njj = 0; njj < 4; njj++) {
                uint32_t b0, b1, b2, b3;
                ldsm4t(b0, b1, b2, b3, vb + (ks*16 + (lane & 15))*144
                                           + (njj*16 + (lane >> 4)*8)*2);
                mma_f16(o[njj*2],   pa0, pa1, pa2, pa3, b0, b1);
                mma_f16(o[njj*2+1], pa0, pa1, pa2, pa3, b2, b3);
            }
        }
    }

    int b = bh >> 4, head = bh & 15;
    float inv0 = 1.0f / l0, inv1 = 1.0f / l1;
    int trow = itile*64 + w*16 + (lane >> 2);
    __half* o0p = out + ((size_t)b*Tt + trow)*Ee + head*HS;
    __half* o1p = o0p + (size_t)8*Ee;
    #pragma unroll
    for (int nj = 0; nj < 8; nj++) {
        int c = nj*8 + 2*(lane & 3);
        *(uint32_t*)&o0p[c] = h2u(o[nj][0]*inv0, o[nj][1]*inv0);
        *(uint32_t*)&o1p[c] = h2u(o[nj][2]*inv1, o[nj][3]*inv1);
    }
}

extern "C" void kernel_launch(void* const* d_in, const int* in_sizes, int n_in,
                              void* d_out, int out_size)
{
    const float* x    = (const float*)d_in[0];
    const float* Wq   = (const float*)d_in[1];
    const float* Wk   = (const float*)d_in[2];
    const float* Wv   = (const float*)d_in[3];
    const float* Wo   = (const float*)d_in[4];
    const float* bo   = (const float*)d_in[5];
    const float* W1   = (const float*)d_in[6];
    const float* b1   = (const float*)d_in[7];
    const float* W2   = (const float*)d_in[8];
    const float* b2   = (const float*)d_in[9];
    const float* ln1w = (const float*)d_in[10];
    const float* ln1b = (const float*)d_in[11];
    const float* ln2w = (const float*)d_in[12];
    const float* ln2b = (const float*)d_in[13];
    float* out = (float*)d_out;

    __half *hP, *qP, *kP, *vP, *uP, *wP;
    float *x1P;
    cudaGetSymbolAddress((void**)&hP,  g_h);
    cudaGetSymbolAddress((void**)&qP,  g_q);
    cudaGetSymbolAddress((void**)&kP,  g_k);
    cudaGetSymbolAddress((void**)&vP,  g_v);
    cudaGetSymbolAddress((void**)&x1P, g_x1);
    cudaGetSymbolAddress((void**)&uP,  g_u);
    cudaGetSymbolAddress((void**)&wP,  g_w);

    cudaFuncSetAttribute(qkv_f16, cudaFuncAttributeMaxDynamicSharedMemorySize, GEMM_SMEM);
    cudaFuncSetAttribute(gemm_f16<false,true,false>, cudaFuncAttributeMaxDynamicSharedMemorySize, GEMM_SMEM);
    cudaFuncSetAttribute(gemm_f16<true,false,true>,  cudaFuncAttributeMaxDynamicSharedMemorySize, GEMM_SMEM);

    // 1) LN1 + all weight converts in ONE launch
    prep<<<NT + 3072, 256>>>(x, ln1w, ln1b, hP,
                             (const float4*)Wq, (const float4*)Wk, (const float4*)Wv,
                             (const float4*)Wo, (const float4*)W1, (const float4*)W2,
                             (uint2*)wP);
    // 2) q,k,v = h @ Wqkv (q pre-scaled by E^-0.5 * log2e)
    qkv_f16<<<dim3(NT/128, 24), 256, GEMM_SMEM>>>(hP, wP, qP, kP, vP);
    // 3) attention -> g_h
    attn_f16<<<dim3(Tt/64, Bb*Hh), 128>>>(qP, kP, vP, hP);
    // 4) x1 = x + attn @ Wo + bo
    gemm_f16<false,true,false><<<dim3(NT/128, Ee/128), 256, GEMM_SMEM>>>(
        hP, wP+WOFF_O, bo, x, x1P, Ee, Ee);
    // 5) h2 = half(LN2(x1))
    ln_h<<<NT, 256>>>(x1P, ln2w, ln2b, qP);
    // 6) u = half(relu(h2 @ W1 + b1))   <-- ncu -s 5 -c 1 lands here
    gemm_f16<true,false,true><<<dim3(NT/128, FF/128), 256, GEMM_SMEM>>>(
        qP, wP+WOFF_1, b1, nullptr, uP, Ee, FF);
    // 7) out = x1 + u @ W2 + b2
    gemm_f16<false,true,false><<<dim3(NT/128, Ee/128), 256, GEMM_SMEM>>>(
        uP, wP+WOFF_2, b2, x1P, out, FF, Ee);
}